// round 1
// baseline (speedup 1.0000x reference)
#include <cuda_runtime.h>
#include <math.h>

// Problem dims (fixed by the reference)
#define D_MODEL 768
#define D_INNER 1536
#define D_STATE 16
#define DT_RANK 96
#define H_FFN   2048
#define LSEQ    2048
#define XPROJ_N (DT_RANK + 2 * D_STATE)  // 128

// ---------------------------------------------------------------------------
// Scratch (no device allocation allowed -> __device__ globals)
// ---------------------------------------------------------------------------
__device__ float g_h   [LSEQ * D_MODEL];
__device__ float g_lin1[LSEQ * D_INNER];   // becomes z after gating (in-place)
__device__ float g_lin2[LSEQ * D_INNER];
__device__ float g_xdbl[LSEQ * XPROJ_N];
__device__ float g_dt  [LSEQ * D_INNER];
__device__ float g_y   [LSEQ * D_INNER];
__device__ float g_x2  [LSEQ * D_MODEL];
__device__ float g_hf  [LSEQ * D_MODEL];
__device__ float g_up  [LSEQ * H_FFN];     // becomes silu(gate)*up (in-place)
__device__ float g_gate[LSEQ * H_FFN];

// ---------------------------------------------------------------------------
// RMSNorm: one block per token, 256 threads, D_MODEL=768
// ---------------------------------------------------------------------------
__global__ __launch_bounds__(256) void rmsnorm_kernel(
    const float* __restrict__ x, const float* __restrict__ w,
    float* __restrict__ out)
{
    const int t = blockIdx.x;
    const float* xr = x + (size_t)t * D_MODEL;
    float* orow = out + (size_t)t * D_MODEL;

    float ss = 0.f;
    for (int i = threadIdx.x; i < D_MODEL; i += 256) {
        float v = xr[i];
        ss = fmaf(v, v, ss);
    }
    #pragma unroll
    for (int o = 16; o > 0; o >>= 1)
        ss += __shfl_xor_sync(0xffffffffu, ss, o);

    __shared__ float sh[8];
    __shared__ float s_rs;
    const int lane = threadIdx.x & 31, wid = threadIdx.x >> 5;
    if (lane == 0) sh[wid] = ss;
    __syncthreads();
    if (threadIdx.x == 0) {
        float tot = 0.f;
        #pragma unroll
        for (int i = 0; i < 8; i++) tot += sh[i];
        s_rs = rsqrtf(tot * (1.0f / D_MODEL) + 1e-6f);
    }
    __syncthreads();
    const float rs = s_rs;
    for (int i = threadIdx.x; i < D_MODEL; i += 256)
        orow[i] = xr[i] * rs * w[i];
}

// ---------------------------------------------------------------------------
// NT SGEMM: C[M,N] = act(A[M,K] @ B[N,K]^T + bias) + addend
//   BM=128, BN=64, BK=16, 256 threads, 8x4 micro-tile per thread.
//   Requires: M % 128 == 0, N % 64 == 0, K % 16 == 0, lda/ldb % 4 == 0.
//   (All shapes in this problem satisfy these.)
//   act: 0 = none, 1 = softplus
// ---------------------------------------------------------------------------
#define GBM 128
#define GBN 64
#define GBK 16

__global__ __launch_bounds__(256) void sgemm_nt(
    const float* __restrict__ A, int lda,
    const float* __restrict__ B, int ldb,
    const float* __restrict__ bias,      // [N] or nullptr
    const float* __restrict__ addend,    // [M, ldadd] or nullptr
    int ldadd,
    float* __restrict__ C, int ldc,
    int K, int act)
{
    __shared__ float As[GBK][GBM];
    __shared__ float Bs[GBK][GBN];

    const int tid  = threadIdx.x;
    const int tx   = tid & 15;   // N direction (16 * 4 = 64)
    const int ty   = tid >> 4;   // M direction (16 * 8 = 128)
    const int row0 = blockIdx.y * GBM;
    const int col0 = blockIdx.x * GBN;

    float acc[8][4];
    #pragma unroll
    for (int i = 0; i < 8; i++)
        #pragma unroll
        for (int j = 0; j < 4; j++) acc[i][j] = 0.f;

    const int ar0 = tid >> 2;           // 0..63
    const int akc = (tid & 3) << 2;     // 0,4,8,12
    const int br  = tid >> 2;           // 0..63
    const int bkc = (tid & 3) << 2;

    for (int k0 = 0; k0 < K; k0 += GBK) {
        #pragma unroll
        for (int j = 0; j < 2; j++) {
            const int ar = ar0 + j * 64;
            float4 v = *reinterpret_cast<const float4*>(
                A + (size_t)(row0 + ar) * lda + k0 + akc);
            As[akc + 0][ar] = v.x;
            As[akc + 1][ar] = v.y;
            As[akc + 2][ar] = v.z;
            As[akc + 3][ar] = v.w;
        }
        {
            float4 v = *reinterpret_cast<const float4*>(
                B + (size_t)(col0 + br) * ldb + k0 + bkc);
            Bs[bkc + 0][br] = v.x;
            Bs[bkc + 1][br] = v.y;
            Bs[bkc + 2][br] = v.z;
            Bs[bkc + 3][br] = v.w;
        }
        __syncthreads();

        #pragma unroll
        for (int kk = 0; kk < GBK; kk++) {
            float4 a0 = *reinterpret_cast<const float4*>(&As[kk][ty << 3]);
            float4 a1 = *reinterpret_cast<const float4*>(&As[kk][(ty << 3) + 4]);
            float4 b0 = *reinterpret_cast<const float4*>(&Bs[kk][tx << 2]);
            const float a[8] = {a0.x, a0.y, a0.z, a0.w, a1.x, a1.y, a1.z, a1.w};
            const float b[4] = {b0.x, b0.y, b0.z, b0.w};
            #pragma unroll
            for (int i = 0; i < 8; i++)
                #pragma unroll
                for (int j = 0; j < 4; j++)
                    acc[i][j] = fmaf(a[i], b[j], acc[i][j]);
        }
        __syncthreads();
    }

    #pragma unroll
    for (int i = 0; i < 8; i++) {
        const int m = row0 + (ty << 3) + i;
        #pragma unroll
        for (int j = 0; j < 4; j++) {
            const int n = col0 + (tx << 2) + j;
            float c = acc[i][j];
            if (bias)  c += bias[n];
            if (act == 1) c = (c > 20.f) ? c : log1pf(expf(c));
            if (addend) c += addend[(size_t)m * ldadd + n];
            C[(size_t)m * ldc + n] = c;
        }
    }
}

// ---------------------------------------------------------------------------
// Elementwise gates
// ---------------------------------------------------------------------------
__global__ void glu_sigmoid_kernel(float* __restrict__ a,
                                   const float* __restrict__ b, int n)
{
    int i = blockIdx.x * blockDim.x + threadIdx.x;
    if (i < n) {
        float g = 1.f / (1.f + expf(-b[i]));
        a[i] *= g;
    }
}

__global__ void glu_silu_kernel(float* __restrict__ up,
                                const float* __restrict__ gate, int n)
{
    int i = blockIdx.x * blockDim.x + threadIdx.x;
    if (i < n) {
        float gv = gate[i];
        float s = gv / (1.f + expf(-gv));   // silu
        up[i] = s * up[i];
    }
}

// ---------------------------------------------------------------------------
// Selective scan: one thread per (d, s). 16 lanes per channel; two channels
// per warp. Sequential over L=2048.
//   h_t = exp(dt*A) * h_{t-1} + dt*z*B_t ;  y_t = sum_s h_t*C_t + D*z
// ---------------------------------------------------------------------------
__global__ __launch_bounds__(256) void scan_kernel(
    const float* __restrict__ dt,     // [L, D_INNER]
    const float* __restrict__ z,      // [L, D_INNER]
    const float* __restrict__ xdbl,   // [L, 128]  (B at 96..111, C at 112..127)
    const float* __restrict__ A_log,  // [D_INNER, 16]
    const float* __restrict__ D_skip, // [D_INNER]
    float* __restrict__ y)            // [L, D_INNER]
{
    const int gid = blockIdx.x * blockDim.x + threadIdx.x;
    const int d = gid >> 4;
    const int s = gid & 15;

    const float Aval = -expf(A_log[d * D_STATE + s]);
    const float Dv = D_skip[d];

    const float* Bp = xdbl + DT_RANK + s;
    const float* Cp = xdbl + DT_RANK + D_STATE + s;

    float h = 0.f;
    #pragma unroll 4
    for (int t = 0; t < LSEQ; t++) {
        const float dtv = dt[(size_t)t * D_INNER + d];
        const float zv  = z [(size_t)t * D_INNER + d];
        const float Bv  = Bp[(size_t)t * XPROJ_N];
        const float Cv  = Cp[(size_t)t * XPROJ_N];

        const float abar = __expf(dtv * Aval);
        h = fmaf(abar, h, dtv * zv * Bv);

        float p = h * Cv;
        p += __shfl_xor_sync(0xffffffffu, p, 8);
        p += __shfl_xor_sync(0xffffffffu, p, 4);
        p += __shfl_xor_sync(0xffffffffu, p, 2);
        p += __shfl_xor_sync(0xffffffffu, p, 1);
        if (s == 0) y[(size_t)t * D_INNER + d] = p + Dv * zv;
    }
}

// ---------------------------------------------------------------------------
// Launch
// ---------------------------------------------------------------------------
extern "C" void kernel_launch(void* const* d_in, const int* in_sizes, int n_in,
                              void* d_out, int out_size)
{
    const float* x        = (const float*)d_in[0];
    const float* w_norm1  = (const float*)d_in[1];
    const float* W_in     = (const float*)d_in[2];
    const float* W_gate   = (const float*)d_in[3];
    const float* W_xproj  = (const float*)d_in[4];
    const float* W_dt     = (const float*)d_in[5];
    const float* b_dt     = (const float*)d_in[6];
    const float* A_log    = (const float*)d_in[7];
    const float* D_skip   = (const float*)d_in[8];
    const float* W_out    = (const float*)d_in[9];
    const float* w_ffn    = (const float*)d_in[10];
    const float* W_up     = (const float*)d_in[11];
    const float* W_gate_f = (const float*)d_in[12];
    const float* W_down   = (const float*)d_in[13];
    float* out = (float*)d_out;

    float *p_h, *p_lin1, *p_lin2, *p_xdbl, *p_dt, *p_y, *p_x2, *p_hf, *p_up, *p_gate;
    cudaGetSymbolAddress((void**)&p_h,    g_h);
    cudaGetSymbolAddress((void**)&p_lin1, g_lin1);
    cudaGetSymbolAddress((void**)&p_lin2, g_lin2);
    cudaGetSymbolAddress((void**)&p_xdbl, g_xdbl);
    cudaGetSymbolAddress((void**)&p_dt,   g_dt);
    cudaGetSymbolAddress((void**)&p_y,    g_y);
    cudaGetSymbolAddress((void**)&p_x2,   g_x2);
    cudaGetSymbolAddress((void**)&p_hf,   g_hf);
    cudaGetSymbolAddress((void**)&p_up,   g_up);
    cudaGetSymbolAddress((void**)&p_gate, g_gate);

    const dim3 blk(256);

    // 1) h = rmsnorm(x, w_norm1)
    rmsnorm_kernel<<<LSEQ, blk>>>(x, w_norm1, p_h);

    // 2) lin1 = h @ W_in.T ; lin2 = h @ W_gate.T
    {
        dim3 g(D_INNER / GBN, LSEQ / GBM);
        sgemm_nt<<<g, blk>>>(p_h, D_MODEL, W_in,   D_MODEL, nullptr, nullptr, 0,
                             p_lin1, D_INNER, D_MODEL, 0);
        sgemm_nt<<<g, blk>>>(p_h, D_MODEL, W_gate, D_MODEL, nullptr, nullptr, 0,
                             p_lin2, D_INNER, D_MODEL, 0);
    }

    // 3) z = lin1 * sigmoid(lin2)   (in-place into lin1)
    {
        int n = LSEQ * D_INNER;
        glu_sigmoid_kernel<<<(n + 255) / 256, blk>>>(p_lin1, p_lin2, n);
    }

    // 4) xdbl = z @ W_xproj.T   [2048, 128]
    {
        dim3 g(XPROJ_N / GBN, LSEQ / GBM);
        sgemm_nt<<<g, blk>>>(p_lin1, D_INNER, W_xproj, D_INNER, nullptr, nullptr, 0,
                             p_xdbl, XPROJ_N, D_INNER, 0);
    }

    // 5) dt = softplus(xdbl[:, :96] @ W_dt.T + b_dt)   [2048, 1536]
    {
        dim3 g(D_INNER / GBN, LSEQ / GBM);
        sgemm_nt<<<g, blk>>>(p_xdbl, XPROJ_N, W_dt, DT_RANK, b_dt, nullptr, 0,
                             p_dt, D_INNER, DT_RANK, 1);
    }

    // 6) selective scan -> y
    scan_kernel<<<(D_INNER * D_STATE) / 256, blk>>>(p_dt, p_lin1, p_xdbl,
                                                    A_log, D_skip, p_y);

    // 7) x2 = x + y @ W_out.T
    {
        dim3 g(D_MODEL / GBN, LSEQ / GBM);
        sgemm_nt<<<g, blk>>>(p_y, D_INNER, W_out, D_INNER, nullptr, x, D_MODEL,
                             p_x2, D_MODEL, D_INNER, 0);
    }

    // 8) hf = rmsnorm(x2, w_ffn)
    rmsnorm_kernel<<<LSEQ, blk>>>(p_x2, w_ffn, p_hf);

    // 9) up = hf @ W_up.T ; gate = hf @ W_gate_ffn.T
    {
        dim3 g(H_FFN / GBN, LSEQ / GBM);
        sgemm_nt<<<g, blk>>>(p_hf, D_MODEL, W_up,     D_MODEL, nullptr, nullptr, 0,
                             p_up,   H_FFN, D_MODEL, 0);
        sgemm_nt<<<g, blk>>>(p_hf, D_MODEL, W_gate_f, D_MODEL, nullptr, nullptr, 0,
                             p_gate, H_FFN, D_MODEL, 0);
    }

    // 10) up = silu(gate) * up
    {
        int n = LSEQ * H_FFN;
        glu_silu_kernel<<<(n + 255) / 256, blk>>>(p_up, p_gate, n);
    }

    // 11) out = x2 + up @ W_down.T
    {
        dim3 g(D_MODEL / GBN, LSEQ / GBM);
        sgemm_nt<<<g, blk>>>(p_up, H_FFN, W_down, H_FFN, nullptr, p_x2, D_MODEL,
                             out, D_MODEL, H_FFN, 0);
    }
}

// round 3
// speedup vs baseline: 1.5924x; 1.5924x over previous
#include <cuda_runtime.h>
#include <cuda_bf16.h>
#include <math.h>
#include <stdint.h>

// ---------------------------------------------------------------------------
// Problem dims
// ---------------------------------------------------------------------------
#define D_MODEL 768
#define D_INNER 1536
#define D_STATE 16
#define DT_RANK 96
#define H_FFN   2048
#define LSEQ    2048
#define XPROJ_N 128
#define KDT_PAD 128   // W_dt K padded 96 -> 128 with zeros

// ---------------------------------------------------------------------------
// Scratch (__device__ globals; no allocations allowed)
// ---------------------------------------------------------------------------
__device__ float g_lin1[LSEQ * D_INNER];   // lin1, then z (fp32, in-place)
__device__ float g_xdbl[LSEQ * XPROJ_N];
__device__ float g_dt  [LSEQ * D_INNER];
__device__ float g_x2  [LSEQ * D_MODEL];
__device__ float g_up  [LSEQ * H_FFN];

// bf16 split pairs (activations)
__device__ __nv_bfloat16 b_h_hi [LSEQ * D_MODEL],  b_h_lo [LSEQ * D_MODEL];
__device__ __nv_bfloat16 b_z_hi [LSEQ * D_INNER],  b_z_lo [LSEQ * D_INNER];
__device__ __nv_bfloat16 b_xd_hi[LSEQ * XPROJ_N],  b_xd_lo[LSEQ * XPROJ_N];
__device__ __nv_bfloat16 b_y_hi [LSEQ * D_INNER],  b_y_lo [LSEQ * D_INNER];
__device__ __nv_bfloat16 b_hf_hi[LSEQ * D_MODEL],  b_hf_lo[LSEQ * D_MODEL];
__device__ __nv_bfloat16 b_v_hi [LSEQ * H_FFN],    b_v_lo [LSEQ * H_FFN];

// bf16 split pairs (weights)
__device__ __nv_bfloat16 w_in_hi [D_INNER * D_MODEL], w_in_lo [D_INNER * D_MODEL];
__device__ __nv_bfloat16 w_gt_hi [D_INNER * D_MODEL], w_gt_lo [D_INNER * D_MODEL];
__device__ __nv_bfloat16 w_x_hi  [XPROJ_N * D_INNER], w_x_lo  [XPROJ_N * D_INNER];
__device__ __nv_bfloat16 w_dt_hi [D_INNER * KDT_PAD], w_dt_lo [D_INNER * KDT_PAD];
__device__ __nv_bfloat16 w_out_hi[D_MODEL * D_INNER], w_out_lo[D_MODEL * D_INNER];
__device__ __nv_bfloat16 w_up_hi [H_FFN * D_MODEL],   w_up_lo [H_FFN * D_MODEL];
__device__ __nv_bfloat16 w_gf_hi [H_FFN * D_MODEL],   w_gf_lo [H_FFN * D_MODEL];
__device__ __nv_bfloat16 w_dn_hi [D_MODEL * H_FFN],   w_dn_lo [D_MODEL * H_FFN];

static __device__ __forceinline__ void split2(float v, __nv_bfloat16* hi, __nv_bfloat16* lo) {
    __nv_bfloat16 h = __float2bfloat16(v);
    *hi = h;
    *lo = __float2bfloat16(v - __bfloat162float(h));
}

static __device__ __forceinline__ uint32_t smem_u32(const void* p) {
    uint32_t a;
    asm("{ .reg .u64 t; cvta.to.shared.u64 t, %1; cvt.u32.u64 %0, t; }"
        : "=r"(a) : "l"(p));
    return a;
}

#define SW128(off) ((off) ^ (((off) >> 3) & 0x70))

#define LDSM4(r, addr)                                                         \
    asm volatile("ldmatrix.sync.aligned.m8n8.x4.shared.b16 {%0,%1,%2,%3}, [%4];" \
        : "=r"((r)[0]), "=r"((r)[1]), "=r"((r)[2]), "=r"((r)[3]) : "r"(addr))

#define MMA16816(c, a, b0, b1)                                                 \
    asm volatile("mma.sync.aligned.m16n8k16.row.col.f32.bf16.bf16.f32 "        \
        "{%0,%1,%2,%3}, {%4,%5,%6,%7}, {%8,%9}, {%0,%1,%2,%3};"                \
        : "+f"((c)[0]), "+f"((c)[1]), "+f"((c)[2]), "+f"((c)[3])               \
        : "r"((a)[0]), "r"((a)[1]), "r"((a)[2]), "r"((a)[3]), "r"(b0), "r"(b1))

#define CP_ASYNC16(sa, ga)                                                     \
    asm volatile("{ .reg .u64 g; cvta.to.global.u64 g, %1; "                   \
                 "cp.async.cg.shared.global [%0], [g], 16; }"                  \
                 :: "r"(sa), "l"(ga))
#define CP_COMMIT()  asm volatile("cp.async.commit_group;" ::: "memory")
#define CP_WAIT1()   asm volatile("cp.async.wait_group 1;" ::: "memory")

// ---------------------------------------------------------------------------
// Weight split kernels
// ---------------------------------------------------------------------------
__global__ void split_kernel(const float* __restrict__ src,
                             __nv_bfloat16* __restrict__ hi,
                             __nv_bfloat16* __restrict__ lo, int n)
{
    int i = blockIdx.x * blockDim.x + threadIdx.x;
    if (i < n) split2(src[i], hi + i, lo + i);
}

__global__ void split_wdt_kernel(const float* __restrict__ src,
                                 __nv_bfloat16* __restrict__ hi,
                                 __nv_bfloat16* __restrict__ lo)
{
    int i = blockIdx.x * blockDim.x + threadIdx.x;
    if (i < D_INNER * KDT_PAD) {
        int r = i / KDT_PAD, c = i % KDT_PAD;
        float v = (c < DT_RANK) ? src[r * DT_RANK + c] : 0.f;
        split2(v, hi + i, lo + i);
    }
}

// ---------------------------------------------------------------------------
// RMSNorm -> bf16 splits. One block per token.
// ---------------------------------------------------------------------------
__global__ __launch_bounds__(256) void rmsnorm_split_kernel(
    const float* __restrict__ x, const float* __restrict__ w,
    __nv_bfloat16* __restrict__ hi, __nv_bfloat16* __restrict__ lo)
{
    const int t = blockIdx.x;
    const float* xr = x + (size_t)t * D_MODEL;

    float ss = 0.f;
    for (int i = threadIdx.x; i < D_MODEL; i += 256) {
        float v = xr[i];
        ss = fmaf(v, v, ss);
    }
    #pragma unroll
    for (int o = 16; o > 0; o >>= 1) ss += __shfl_xor_sync(0xffffffffu, ss, o);

    __shared__ float sh[8];
    __shared__ float s_rs;
    const int lane = threadIdx.x & 31, wid = threadIdx.x >> 5;
    if (lane == 0) sh[wid] = ss;
    __syncthreads();
    if (threadIdx.x == 0) {
        float tot = 0.f;
        #pragma unroll
        for (int i = 0; i < 8; i++) tot += sh[i];
        s_rs = rsqrtf(tot * (1.0f / D_MODEL) + 1e-6f);
    }
    __syncthreads();
    const float rs = s_rs;
    for (int i = threadIdx.x; i < D_MODEL; i += 256) {
        float v = xr[i] * rs * w[i];
        size_t o = (size_t)t * D_MODEL + i;
        split2(v, hi + o, lo + o);
    }
}

// ---------------------------------------------------------------------------
// bf16-split GEMM on mma.sync (HMMA): C[M,N] = f(A[M,K] @ B[N,K]^T)
//   3-term split: Ah*Bh + Ah*Bl + Al*Bh, fp32 accumulate.
//   CTA tile 128x128, BK=64, 256 threads (8 warps = 4M x 2N).
//   SW128-swizzled smem, 2-stage cp.async pipeline, smem-staged epilogue.
//   op: 0 none | 1 bias+softplus | 2 aux*sigmoid(acc) | 3 acc+aux | 4 silu(acc)*aux
// ---------------------------------------------------------------------------
#define TILE16K 16384                  // one 128x64 bf16 tile (128B rows)
#define STAGE_B (4 * TILE16K)          // Ah, Al, Bh, Bl
#define GEMM_SMEM (2 * STAGE_B)        // 131072 (epilogue reuses: 128*132*4)

__global__ __launch_bounds__(256) void gemm_bf3(
    const __nv_bfloat16* __restrict__ Ah, const __nv_bfloat16* __restrict__ Al,
    const __nv_bfloat16* __restrict__ Bh, const __nv_bfloat16* __restrict__ Bl,
    int K, int N,
    float* __restrict__ outF,
    __nv_bfloat16* __restrict__ outH, __nv_bfloat16* __restrict__ outL,
    const float* __restrict__ aux, const float* __restrict__ bias, int op)
{
    extern __shared__ char smem[];
    const uint32_t sb = smem_u32(smem);
    const int tid  = threadIdx.x;
    const int lane = tid & 31;
    const int warp = tid >> 5;
    const int m0 = blockIdx.y * 128;
    const int n0 = blockIdx.x * 128;
    const int wm0 = (warp >> 1) * 32;   // warp M offset (4 warps in M)
    const int wn0 = (warp & 1) * 64;    // warp N offset (2 warps in N)

    const int nch = K >> 6;

    float acc[2][8][4];
    #pragma unroll
    for (int mt = 0; mt < 2; mt++)
        #pragma unroll
        for (int nt = 0; nt < 8; nt++)
            #pragma unroll
            for (int r = 0; r < 4; r++) acc[mt][nt][r] = 0.f;

    // ---- loaders ----
    auto load_stage = [&](int s, int ci) {
        const int k0 = ci << 6;
        const uint32_t sbase = sb + s * STAGE_B;
        #pragma unroll
        for (int arr = 0; arr < 4; arr++) {
            const __nv_bfloat16* src = (arr == 0) ? Ah : (arr == 1) ? Al
                                     : (arr == 2) ? Bh : Bl;
            const int r0 = (arr < 2) ? m0 : n0;
            #pragma unroll
            for (int jj = 0; jj < 4; jj++) {
                const int idx = jj * 256 + tid;    // 0..1023
                const int row = idx >> 3;
                const int c16 = idx & 7;
                const __nv_bfloat16* g = src + (size_t)(r0 + row) * K + k0 + c16 * 8;
                const uint32_t sa = sbase + arr * TILE16K
                                  + SW128((uint32_t)(row * 128 + c16 * 16));
                CP_ASYNC16(sa, g);
            }
        }
    };

    // lane-fixed ldmatrix offsets
    const int arow = ((lane >> 3) & 1) * 8 + (lane & 7);
    const int akb  = (lane >> 4) * 16;
    const int brow = ((lane >> 4) & 1) * 8 + (lane & 7);
    const int bkb  = ((lane >> 3) & 1) * 16;

    auto compute = [&](int s) {
        const uint32_t sA_h = sb + s * STAGE_B;
        const uint32_t sA_l = sA_h + TILE16K;
        const uint32_t sB_h = sA_h + 2 * TILE16K;
        const uint32_t sB_l = sA_h + 3 * TILE16K;
        #pragma unroll
        for (int ks = 0; ks < 4; ks++) {
            uint32_t a_h[2][4], a_l[2][4], b_h[4][4], b_l[4][4];
            #pragma unroll
            for (int mt = 0; mt < 2; mt++) {
                const uint32_t off = SW128(
                    (uint32_t)((wm0 + mt * 16 + arow) * 128 + ks * 32 + akb));
                LDSM4(a_h[mt], sA_h + off);
                LDSM4(a_l[mt], sA_l + off);
            }
            #pragma unroll
            for (int j = 0; j < 4; j++) {
                const uint32_t off = SW128(
                    (uint32_t)((wn0 + j * 16 + brow) * 128 + ks * 32 + bkb));
                LDSM4(b_h[j], sB_h + off);
                LDSM4(b_l[j], sB_l + off);
            }
            #pragma unroll
            for (int mt = 0; mt < 2; mt++)
                #pragma unroll
                for (int nt = 0; nt < 8; nt++) {
                    const uint32_t bh0 = b_h[nt >> 1][(nt & 1) * 2];
                    const uint32_t bh1 = b_h[nt >> 1][(nt & 1) * 2 + 1];
                    const uint32_t bl0 = b_l[nt >> 1][(nt & 1) * 2];
                    const uint32_t bl1 = b_l[nt >> 1][(nt & 1) * 2 + 1];
                    MMA16816(acc[mt][nt], a_h[mt], bh0, bh1);
                    MMA16816(acc[mt][nt], a_h[mt], bl0, bl1);
                    MMA16816(acc[mt][nt], a_l[mt], bh0, bh1);
                }
        }
    };

    // ---- pipeline ----
    load_stage(0, 0); CP_COMMIT();
    load_stage(1, 1); CP_COMMIT();
    for (int i = 0; i < nch; i++) {
        CP_WAIT1();
        __syncthreads();
        compute(i & 1);
        __syncthreads();
        if (i + 2 < nch) load_stage(i & 1, i + 2);
        CP_COMMIT();
    }
    __syncthreads();

    // ---- epilogue: stage C through smem for coalesced gmem writes ----
    float* smC = reinterpret_cast<float*>(smem);   // [128][132]
    #pragma unroll
    for (int mt = 0; mt < 2; mt++)
        #pragma unroll
        for (int nt = 0; nt < 8; nt++) {
            const int row = wm0 + mt * 16 + (lane >> 2);
            const int col = wn0 + nt * 8 + (lane & 3) * 2;
            *reinterpret_cast<float2*>(&smC[row * 132 + col]) =
                make_float2(acc[mt][nt][0], acc[mt][nt][1]);
            *reinterpret_cast<float2*>(&smC[(row + 8) * 132 + col]) =
                make_float2(acc[mt][nt][2], acc[mt][nt][3]);
        }
    __syncthreads();

    #pragma unroll 4
    for (int e = tid; e < 128 * 128; e += 256) {
        const int row = e >> 7, col = e & 127;
        float v = smC[row * 132 + col];
        const size_t ro = (size_t)(m0 + row) * N + (n0 + col);
        if (op == 1) {
            v += bias[n0 + col];
            v = (v > 20.f) ? v : log1pf(__expf(v));
        } else if (op == 2) {
            v = aux[ro] * (1.f / (1.f + __expf(-v)));
        } else if (op == 3) {
            v += aux[ro];
        } else if (op == 4) {
            float s = v * (1.f / (1.f + __expf(-v)));
            v = s * aux[ro];
        }
        if (outF) outF[ro] = v;
        if (outH) split2(v, outH + ro, outL + ro);
    }
}

// ---------------------------------------------------------------------------
// Selective scan: one thread per (d, s); sequential over L. Writes y splits.
// ---------------------------------------------------------------------------
__global__ __launch_bounds__(256) void scan_kernel(
    const float* __restrict__ dt,     // [L, D_INNER]
    const float* __restrict__ z,      // [L, D_INNER]
    const float* __restrict__ xdbl,   // [L, 128]
    const float* __restrict__ A_log,  // [D_INNER, 16]
    const float* __restrict__ D_skip, // [D_INNER]
    __nv_bfloat16* __restrict__ y_hi, __nv_bfloat16* __restrict__ y_lo)
{
    const int gid = blockIdx.x * blockDim.x + threadIdx.x;
    const int d = gid >> 4;
    const int s = gid & 15;

    const float Aval = -expf(A_log[d * D_STATE + s]);
    const float Dv = D_skip[d];

    const float* Bp = xdbl + DT_RANK + s;
    const float* Cp = xdbl + DT_RANK + D_STATE + s;

    float h = 0.f;
    #pragma unroll 4
    for (int t = 0; t < LSEQ; t++) {
        const float dtv = dt[(size_t)t * D_INNER + d];
        const float zv  = z [(size_t)t * D_INNER + d];
        const float Bv  = Bp[(size_t)t * XPROJ_N];
        const float Cv  = Cp[(size_t)t * XPROJ_N];

        const float abar = __expf(dtv * Aval);
        h = fmaf(abar, h, dtv * zv * Bv);

        float p = h * Cv;
        p += __shfl_xor_sync(0xffffffffu, p, 8);
        p += __shfl_xor_sync(0xffffffffu, p, 4);
        p += __shfl_xor_sync(0xffffffffu, p, 2);
        p += __shfl_xor_sync(0xffffffffu, p, 1);
        if (s == 0) {
            float yv = p + Dv * zv;
            size_t o = (size_t)t * D_INNER + d;
            split2(yv, y_hi + o, y_lo + o);
        }
    }
}

// ---------------------------------------------------------------------------
// Launch
// ---------------------------------------------------------------------------
extern "C" void kernel_launch(void* const* d_in, const int* in_sizes, int n_in,
                              void* d_out, int out_size)
{
    const float* x        = (const float*)d_in[0];
    const float* w_norm1  = (const float*)d_in[1];
    const float* W_in     = (const float*)d_in[2];
    const float* W_gate   = (const float*)d_in[3];
    const float* W_xproj  = (const float*)d_in[4];
    const float* W_dt     = (const float*)d_in[5];
    const float* b_dt     = (const float*)d_in[6];
    const float* A_log    = (const float*)d_in[7];
    const float* D_skip   = (const float*)d_in[8];
    const float* W_out    = (const float*)d_in[9];
    const float* w_ffn    = (const float*)d_in[10];
    const float* W_up     = (const float*)d_in[11];
    const float* W_gate_f = (const float*)d_in[12];
    const float* W_down   = (const float*)d_in[13];
    float* out = (float*)d_out;

    float *p_lin1, *p_xdbl, *p_dt, *p_x2, *p_up;
    cudaGetSymbolAddress((void**)&p_lin1, g_lin1);
    cudaGetSymbolAddress((void**)&p_xdbl, g_xdbl);
    cudaGetSymbolAddress((void**)&p_dt,   g_dt);
    cudaGetSymbolAddress((void**)&p_x2,   g_x2);
    cudaGetSymbolAddress((void**)&p_up,   g_up);

    __nv_bfloat16 *hH,*hL,*zH,*zL,*xdH,*xdL,*yH,*yL,*hfH,*hfL,*vH,*vL;
    cudaGetSymbolAddress((void**)&hH,  b_h_hi);  cudaGetSymbolAddress((void**)&hL,  b_h_lo);
    cudaGetSymbolAddress((void**)&zH,  b_z_hi);  cudaGetSymbolAddress((void**)&zL,  b_z_lo);
    cudaGetSymbolAddress((void**)&xdH, b_xd_hi); cudaGetSymbolAddress((void**)&xdL, b_xd_lo);
    cudaGetSymbolAddress((void**)&yH,  b_y_hi);  cudaGetSymbolAddress((void**)&yL,  b_y_lo);
    cudaGetSymbolAddress((void**)&hfH, b_hf_hi); cudaGetSymbolAddress((void**)&hfL, b_hf_lo);
    cudaGetSymbolAddress((void**)&vH,  b_v_hi);  cudaGetSymbolAddress((void**)&vL,  b_v_lo);

    __nv_bfloat16 *winH,*winL,*wgtH,*wgtL,*wxH,*wxL,*wdtH,*wdtL,*woH,*woL,*wuH,*wuL,*wgfH,*wgfL,*wdnH,*wdnL;
    cudaGetSymbolAddress((void**)&winH, w_in_hi);  cudaGetSymbolAddress((void**)&winL, w_in_lo);
    cudaGetSymbolAddress((void**)&wgtH, w_gt_hi);  cudaGetSymbolAddress((void**)&wgtL, w_gt_lo);
    cudaGetSymbolAddress((void**)&wxH,  w_x_hi);   cudaGetSymbolAddress((void**)&wxL,  w_x_lo);
    cudaGetSymbolAddress((void**)&wdtH, w_dt_hi);  cudaGetSymbolAddress((void**)&wdtL, w_dt_lo);
    cudaGetSymbolAddress((void**)&woH,  w_out_hi); cudaGetSymbolAddress((void**)&woL,  w_out_lo);
    cudaGetSymbolAddress((void**)&wuH,  w_up_hi);  cudaGetSymbolAddress((void**)&wuL,  w_up_lo);
    cudaGetSymbolAddress((void**)&wgfH, w_gf_hi);  cudaGetSymbolAddress((void**)&wgfL, w_gf_lo);
    cudaGetSymbolAddress((void**)&wdnH, w_dn_hi);  cudaGetSymbolAddress((void**)&wdnL, w_dn_lo);

    static bool attr_set = false;
    cudaFuncSetAttribute(gemm_bf3, cudaFuncAttributeMaxDynamicSharedMemorySize, GEMM_SMEM);
    (void)attr_set;

    const dim3 blk(256);
    #define SPLIT(src, hi, lo, n) split_kernel<<<((n) + 255) / 256, blk>>>(src, hi, lo, n)

    // weight splits
    SPLIT(W_in,     winH, winL, D_INNER * D_MODEL);
    SPLIT(W_gate,   wgtH, wgtL, D_INNER * D_MODEL);
    SPLIT(W_xproj,  wxH,  wxL,  XPROJ_N * D_INNER);
    split_wdt_kernel<<<(D_INNER * KDT_PAD + 255) / 256, blk>>>(W_dt, wdtH, wdtL);
    SPLIT(W_out,    woH,  woL,  D_MODEL * D_INNER);
    SPLIT(W_up,     wuH,  wuL,  H_FFN * D_MODEL);
    SPLIT(W_gate_f, wgfH, wgfL, H_FFN * D_MODEL);
    SPLIT(W_down,   wdnH, wdnL, D_MODEL * H_FFN);

    // 1) h = rmsnorm(x) -> splits
    rmsnorm_split_kernel<<<LSEQ, blk>>>(x, w_norm1, hH, hL);

    // 2) lin1 = h @ W_in^T  (fp32 only)
    gemm_bf3<<<dim3(D_INNER / 128, LSEQ / 128), blk, GEMM_SMEM>>>(
        hH, hL, winH, winL, D_MODEL, D_INNER,
        p_lin1, nullptr, nullptr, nullptr, nullptr, 0);

    // 3) z = lin1 * sigmoid(h @ W_gate^T)  (fp32 in-place + splits)
    gemm_bf3<<<dim3(D_INNER / 128, LSEQ / 128), blk, GEMM_SMEM>>>(
        hH, hL, wgtH, wgtL, D_MODEL, D_INNER,
        p_lin1, zH, zL, p_lin1, nullptr, 2);

    // 4) xdbl = z @ W_xproj^T  (fp32 + splits)
    gemm_bf3<<<dim3(XPROJ_N / 128, LSEQ / 128), blk, GEMM_SMEM>>>(
        zH, zL, wxH, wxL, D_INNER, XPROJ_N,
        p_xdbl, xdH, xdL, nullptr, nullptr, 0);

    // 5) dt = softplus(xdbl @ W_dt_pad^T + b_dt)  (fp32 only)
    gemm_bf3<<<dim3(D_INNER / 128, LSEQ / 128), blk, GEMM_SMEM>>>(
        xdH, xdL, wdtH, wdtL, KDT_PAD, D_INNER,
        p_dt, nullptr, nullptr, nullptr, b_dt, 1);

    // 6) selective scan -> y splits
    scan_kernel<<<(D_INNER * D_STATE) / 256, blk>>>(p_dt, p_lin1, p_xdbl,
                                                    A_log, D_skip, yH, yL);

    // 7) x2 = x + y @ W_out^T  (fp32)
    gemm_bf3<<<dim3(D_MODEL / 128, LSEQ / 128), blk, GEMM_SMEM>>>(
        yH, yL, woH, woL, D_INNER, D_MODEL,
        p_x2, nullptr, nullptr, x, nullptr, 3);

    // 8) hf = rmsnorm(x2) -> splits
    rmsnorm_split_kernel<<<LSEQ, blk>>>(p_x2, w_ffn, hfH, hfL);

    // 9) up = hf @ W_up^T  (fp32)
    gemm_bf3<<<dim3(H_FFN / 128, LSEQ / 128), blk, GEMM_SMEM>>>(
        hfH, hfL, wuH, wuL, D_MODEL, H_FFN,
        p_up, nullptr, nullptr, nullptr, nullptr, 0);

    // 10) v = silu(hf @ W_gate_ffn^T) * up  (splits only)
    gemm_bf3<<<dim3(H_FFN / 128, LSEQ / 128), blk, GEMM_SMEM>>>(
        hfH, hfL, wgfH, wgfL, D_MODEL, H_FFN,
        nullptr, vH, vL, p_up, nullptr, 4);

    // 11) out = x2 + v @ W_down^T
    gemm_bf3<<<dim3(D_MODEL / 128, LSEQ / 128), blk, GEMM_SMEM>>>(
        vH, vL, wdnH, wdnL, H_FFN, D_MODEL,
        out, nullptr, nullptr, p_x2, nullptr, 3);
}

// round 4
// speedup vs baseline: 1.9277x; 1.2106x over previous
#include <cuda_runtime.h>
#include <cuda_bf16.h>
#include <math.h>
#include <stdint.h>

// ---------------------------------------------------------------------------
// Problem dims
// ---------------------------------------------------------------------------
#define D_MODEL 768
#define D_INNER 1536
#define D_STATE 16
#define DT_RANK 96
#define H_FFN   2048
#define LSEQ    2048
#define XPROJ_N 128
#define KDT_PAD 128

// ---------------------------------------------------------------------------
// Scratch
// ---------------------------------------------------------------------------
__device__ float g_lin1[LSEQ * D_INNER];   // raw in-proj, then z (in-place)
__device__ float g_lin2[LSEQ * D_INNER];   // raw gate-proj
__device__ float g_xdbl[LSEQ * XPROJ_N];
__device__ float g_dt  [LSEQ * D_INNER];
__device__ float g_x2  [LSEQ * D_MODEL];
__device__ float g_up  [LSEQ * H_FFN];
__device__ float g_gate[LSEQ * H_FFN];

__device__ __nv_bfloat16 b_h_hi [LSEQ * D_MODEL],  b_h_lo [LSEQ * D_MODEL];
__device__ __nv_bfloat16 b_z_hi [LSEQ * D_INNER],  b_z_lo [LSEQ * D_INNER];
__device__ __nv_bfloat16 b_xd_hi[LSEQ * XPROJ_N],  b_xd_lo[LSEQ * XPROJ_N];
__device__ __nv_bfloat16 b_y_hi [LSEQ * D_INNER],  b_y_lo [LSEQ * D_INNER];
__device__ __nv_bfloat16 b_hf_hi[LSEQ * D_MODEL],  b_hf_lo[LSEQ * D_MODEL];
__device__ __nv_bfloat16 b_v_hi [LSEQ * H_FFN],    b_v_lo [LSEQ * H_FFN];

__device__ __nv_bfloat16 w_in_hi [D_INNER * D_MODEL], w_in_lo [D_INNER * D_MODEL];
__device__ __nv_bfloat16 w_gt_hi [D_INNER * D_MODEL], w_gt_lo [D_INNER * D_MODEL];
__device__ __nv_bfloat16 w_x_hi  [XPROJ_N * D_INNER], w_x_lo  [XPROJ_N * D_INNER];
__device__ __nv_bfloat16 w_dt_hi [D_INNER * KDT_PAD], w_dt_lo [D_INNER * KDT_PAD];
__device__ __nv_bfloat16 w_out_hi[D_MODEL * D_INNER], w_out_lo[D_MODEL * D_INNER];
__device__ __nv_bfloat16 w_up_hi [H_FFN * D_MODEL],   w_up_lo [H_FFN * D_MODEL];
__device__ __nv_bfloat16 w_gf_hi [H_FFN * D_MODEL],   w_gf_lo [H_FFN * D_MODEL];
__device__ __nv_bfloat16 w_dn_hi [D_MODEL * H_FFN],   w_dn_lo [D_MODEL * H_FFN];

static __device__ __forceinline__ void split2(float v, __nv_bfloat16* hi, __nv_bfloat16* lo) {
    __nv_bfloat16 h = __float2bfloat16(v);
    *hi = h;
    *lo = __float2bfloat16(v - __bfloat162float(h));
}

static __device__ __forceinline__ uint32_t smem_u32(const void* p) {
    uint32_t a;
    asm("{ .reg .u64 t; cvta.to.shared.u64 t, %1; cvt.u32.u64 %0, t; }"
        : "=r"(a) : "l"(p));
    return a;
}

#define SW128(off) ((off) ^ (((off) >> 3) & 0x70))

#define LDSM4(r, addr)                                                         \
    asm volatile("ldmatrix.sync.aligned.m8n8.x4.shared.b16 {%0,%1,%2,%3}, [%4];" \
        : "=r"((r)[0]), "=r"((r)[1]), "=r"((r)[2]), "=r"((r)[3]) : "r"(addr))

#define MMA16816(c, a, b0, b1)                                                 \
    asm volatile("mma.sync.aligned.m16n8k16.row.col.f32.bf16.bf16.f32 "        \
        "{%0,%1,%2,%3}, {%4,%5,%6,%7}, {%8,%9}, {%0,%1,%2,%3};"                \
        : "+f"((c)[0]), "+f"((c)[1]), "+f"((c)[2]), "+f"((c)[3])               \
        : "r"((a)[0]), "r"((a)[1]), "r"((a)[2]), "r"((a)[3]), "r"(b0), "r"(b1))

#define CP_ASYNC16(sa, ga)                                                     \
    asm volatile("{ .reg .u64 g; cvta.to.global.u64 g, %1; "                   \
                 "cp.async.cg.shared.global [%0], [g], 16; }"                  \
                 :: "r"(sa), "l"(ga))
#define CP_COMMIT()  asm volatile("cp.async.commit_group;" ::: "memory")
#define CP_WAIT1()   asm volatile("cp.async.wait_group 1;" ::: "memory")

// ---------------------------------------------------------------------------
// Weight splits (vectorized) + misc elementwise
// ---------------------------------------------------------------------------
__global__ void split_kernel(const float* __restrict__ src,
                             __nv_bfloat16* __restrict__ hi,
                             __nv_bfloat16* __restrict__ lo, int n4)
{
    int i = blockIdx.x * blockDim.x + threadIdx.x;
    if (i < n4) {
        float4 v = reinterpret_cast<const float4*>(src)[i];
        int b = i * 4;
        split2(v.x, hi + b + 0, lo + b + 0);
        split2(v.y, hi + b + 1, lo + b + 1);
        split2(v.z, hi + b + 2, lo + b + 2);
        split2(v.w, hi + b + 3, lo + b + 3);
    }
}

__global__ void split_wdt_kernel(const float* __restrict__ src,
                                 __nv_bfloat16* __restrict__ hi,
                                 __nv_bfloat16* __restrict__ lo)
{
    int i = blockIdx.x * blockDim.x + threadIdx.x;
    if (i < D_INNER * KDT_PAD) {
        int r = i / KDT_PAD, c = i % KDT_PAD;
        float v = (c < DT_RANK) ? src[r * DT_RANK + c] : 0.f;
        split2(v, hi + i, lo + i);
    }
}

// z = lin1 * sigmoid(lin2); write z fp32 (in-place over lin1) + bf16 splits
__global__ void gate_split_kernel(float* __restrict__ lin1,
                                  const float* __restrict__ lin2,
                                  __nv_bfloat16* __restrict__ zH,
                                  __nv_bfloat16* __restrict__ zL, int n4)
{
    int i = blockIdx.x * blockDim.x + threadIdx.x;
    if (i < n4) {
        float4 a = reinterpret_cast<float4*>(lin1)[i];
        float4 g = reinterpret_cast<const float4*>(lin2)[i];
        a.x *= 1.f / (1.f + __expf(-g.x));
        a.y *= 1.f / (1.f + __expf(-g.y));
        a.z *= 1.f / (1.f + __expf(-g.z));
        a.w *= 1.f / (1.f + __expf(-g.w));
        reinterpret_cast<float4*>(lin1)[i] = a;
        int b = i * 4;
        split2(a.x, zH + b + 0, zL + b + 0);
        split2(a.y, zH + b + 1, zL + b + 1);
        split2(a.z, zH + b + 2, zL + b + 2);
        split2(a.w, zH + b + 3, zL + b + 3);
    }
}

// v = silu(gate) * up -> bf16 splits only
__global__ void silu_mul_split_kernel(const float* __restrict__ up,
                                      const float* __restrict__ gate,
                                      __nv_bfloat16* __restrict__ vH,
                                      __nv_bfloat16* __restrict__ vL, int n4)
{
    int i = blockIdx.x * blockDim.x + threadIdx.x;
    if (i < n4) {
        float4 u = reinterpret_cast<const float4*>(up)[i];
        float4 g = reinterpret_cast<const float4*>(gate)[i];
        float4 v;
        v.x = g.x / (1.f + __expf(-g.x)) * u.x;
        v.y = g.y / (1.f + __expf(-g.y)) * u.y;
        v.z = g.z / (1.f + __expf(-g.z)) * u.z;
        v.w = g.w / (1.f + __expf(-g.w)) * u.w;
        int b = i * 4;
        split2(v.x, vH + b + 0, vL + b + 0);
        split2(v.y, vH + b + 1, vL + b + 1);
        split2(v.z, vH + b + 2, vL + b + 2);
        split2(v.w, vH + b + 3, vL + b + 3);
    }
}

// ---------------------------------------------------------------------------
// RMSNorm -> bf16 splits
// ---------------------------------------------------------------------------
__global__ __launch_bounds__(256) void rmsnorm_split_kernel(
    const float* __restrict__ x, const float* __restrict__ w,
    __nv_bfloat16* __restrict__ hi, __nv_bfloat16* __restrict__ lo)
{
    const int t = blockIdx.x;
    const float* xr = x + (size_t)t * D_MODEL;

    float ss = 0.f;
    for (int i = threadIdx.x; i < D_MODEL; i += 256) {
        float v = xr[i];
        ss = fmaf(v, v, ss);
    }
    #pragma unroll
    for (int o = 16; o > 0; o >>= 1) ss += __shfl_xor_sync(0xffffffffu, ss, o);

    __shared__ float sh[8];
    __shared__ float s_rs;
    const int lane = threadIdx.x & 31, wid = threadIdx.x >> 5;
    if (lane == 0) sh[wid] = ss;
    __syncthreads();
    if (threadIdx.x == 0) {
        float tot = 0.f;
        #pragma unroll
        for (int i = 0; i < 8; i++) tot += sh[i];
        s_rs = rsqrtf(tot * (1.0f / D_MODEL) + 1e-6f);
    }
    __syncthreads();
    const float rs = s_rs;
    for (int i = threadIdx.x; i < D_MODEL; i += 256) {
        float v = xr[i] * rs * w[i];
        size_t o = (size_t)t * D_MODEL + i;
        split2(v, hi + o, lo + o);
    }
}

// ---------------------------------------------------------------------------
// bf16-split GEMM on mma.sync: C[M,N] = f(A[M,K] @ B[N,K]^T)
//   Template BM in {128, 64}. BN=128, KC=64, 256 threads.
//   BM=128: warps 4Mx2N (tile 32x64). BM=64: warps 2Mx4N (tile 32x32).
//   gridDim.z==2 batches a second (B2, out2) GEMM sharing A.
//   op: 0 none | 1 bias+softplus | 3 acc+aux
// ---------------------------------------------------------------------------
template<int BM>
__global__ __launch_bounds__(256) void gemm_bf3(
    const __nv_bfloat16* __restrict__ Ah, const __nv_bfloat16* __restrict__ Al,
    const __nv_bfloat16* __restrict__ Bh_, const __nv_bfloat16* __restrict__ Bl_,
    const __nv_bfloat16* __restrict__ B2h, const __nv_bfloat16* __restrict__ B2l,
    int K, int N,
    float* __restrict__ outF_, float* __restrict__ out2F,
    __nv_bfloat16* __restrict__ outH, __nv_bfloat16* __restrict__ outL,
    const float* __restrict__ aux, const float* __restrict__ bias, int op)
{
    constexpr int WN  = (BM == 128) ? 2 : 4;     // warps in N
    constexpr int NT  = 128 / WN / 8;            // 8 or 4 n-subtiles per warp
    constexpr int ATB = BM * 128;                // A tile bytes (rows * 64 bf16 * 2B)
    constexpr int BTB = 128 * 128;               // B tile bytes
    constexpr int STAGE_B = 2 * ATB + 2 * BTB;

    const __nv_bfloat16* Bh = blockIdx.z ? B2h : Bh_;
    const __nv_bfloat16* Bl = blockIdx.z ? B2l : Bl_;
    float* outF = blockIdx.z ? out2F : outF_;

    extern __shared__ char smem[];
    const uint32_t sb = smem_u32(smem);
    const int tid  = threadIdx.x;
    const int lane = tid & 31;
    const int warp = tid >> 5;
    const int m0 = blockIdx.y * BM;
    const int n0 = blockIdx.x * 128;
    const int wm0 = (warp / WN) * 32;
    const int wn0 = (warp % WN) * (128 / WN);

    const int nch = K >> 6;

    float acc[2][NT][4];
    #pragma unroll
    for (int mt = 0; mt < 2; mt++)
        #pragma unroll
        for (int nt = 0; nt < NT; nt++)
            #pragma unroll
            for (int r = 0; r < 4; r++) acc[mt][nt][r] = 0.f;

    auto load_stage = [&](int s, int ci) {
        const int k0 = ci << 6;
        const uint32_t sbase = sb + s * STAGE_B;
        #pragma unroll
        for (int arr = 0; arr < 4; arr++) {
            const __nv_bfloat16* src = (arr == 0) ? Ah : (arr == 1) ? Al
                                     : (arr == 2) ? Bh : Bl;
            const int r0 = (arr < 2) ? m0 : n0;
            const int nvec = ((arr < 2) ? BM : 128) * 8;   // 16B vectors
            const uint32_t abase = sbase + ((arr == 0) ? 0 : (arr == 1) ? ATB
                                  : (arr == 2) ? 2 * ATB : 2 * ATB + BTB);
            #pragma unroll
            for (int jj = 0; jj < nvec / 256; jj++) {
                const int idx = jj * 256 + tid;
                const int row = idx >> 3;
                const int c16 = idx & 7;
                const __nv_bfloat16* g = src + (size_t)(r0 + row) * K + k0 + c16 * 8;
                const uint32_t sa = abase + SW128((uint32_t)(row * 128 + c16 * 16));
                CP_ASYNC16(sa, g);
            }
        }
    };

    const int arow = ((lane >> 3) & 1) * 8 + (lane & 7);
    const int akb  = (lane >> 4) * 16;
    const int brow = ((lane >> 4) & 1) * 8 + (lane & 7);
    const int bkb  = ((lane >> 3) & 1) * 16;

    auto compute = [&](int s) {
        const uint32_t sA_h = sb + s * STAGE_B;
        const uint32_t sA_l = sA_h + ATB;
        const uint32_t sB_h = sA_h + 2 * ATB;
        const uint32_t sB_l = sB_h + BTB;
        #pragma unroll
        for (int ks = 0; ks < 4; ks++) {
            uint32_t a_h[2][4], a_l[2][4], b_h[NT / 2][4], b_l[NT / 2][4];
            #pragma unroll
            for (int mt = 0; mt < 2; mt++) {
                const uint32_t off = SW128(
                    (uint32_t)((wm0 + mt * 16 + arow) * 128 + ks * 32 + akb));
                LDSM4(a_h[mt], sA_h + off);
                LDSM4(a_l[mt], sA_l + off);
            }
            #pragma unroll
            for (int j = 0; j < NT / 2; j++) {
                const uint32_t off = SW128(
                    (uint32_t)((wn0 + j * 16 + brow) * 128 + ks * 32 + bkb));
                LDSM4(b_h[j], sB_h + off);
                LDSM4(b_l[j], sB_l + off);
            }
            #pragma unroll
            for (int mt = 0; mt < 2; mt++)
                #pragma unroll
                for (int nt = 0; nt < NT; nt++) {
                    const uint32_t bh0 = b_h[nt >> 1][(nt & 1) * 2];
                    const uint32_t bh1 = b_h[nt >> 1][(nt & 1) * 2 + 1];
                    const uint32_t bl0 = b_l[nt >> 1][(nt & 1) * 2];
                    const uint32_t bl1 = b_l[nt >> 1][(nt & 1) * 2 + 1];
                    MMA16816(acc[mt][nt], a_h[mt], bh0, bh1);
                    MMA16816(acc[mt][nt], a_h[mt], bl0, bl1);
                    MMA16816(acc[mt][nt], a_l[mt], bh0, bh1);
                }
        }
    };

    load_stage(0, 0); CP_COMMIT();
    load_stage(1, 1); CP_COMMIT();
    for (int i = 0; i < nch; i++) {
        CP_WAIT1();
        __syncthreads();
        compute(i & 1);
        __syncthreads();
        if (i + 2 < nch) load_stage(i & 1, i + 2);
        CP_COMMIT();
    }
    __syncthreads();

    // epilogue via smem for coalesced stores
    float* smC = reinterpret_cast<float*>(smem);   // [BM][132]
    #pragma unroll
    for (int mt = 0; mt < 2; mt++)
        #pragma unroll
        for (int nt = 0; nt < NT; nt++) {
            const int row = wm0 + mt * 16 + (lane >> 2);
            const int col = wn0 + nt * 8 + (lane & 3) * 2;
            *reinterpret_cast<float2*>(&smC[row * 132 + col]) =
                make_float2(acc[mt][nt][0], acc[mt][nt][1]);
            *reinterpret_cast<float2*>(&smC[(row + 8) * 132 + col]) =
                make_float2(acc[mt][nt][2], acc[mt][nt][3]);
        }
    __syncthreads();

    #pragma unroll 4
    for (int e = tid; e < BM * 128; e += 256) {
        const int row = e >> 7, col = e & 127;
        float v = smC[row * 132 + col];
        const size_t ro = (size_t)(m0 + row) * N + (n0 + col);
        if (op == 1) {
            v += bias[n0 + col];
            v = (v > 20.f) ? v : log1pf(__expf(v));
        } else if (op == 3) {
            v += aux[ro];
        }
        if (outF) outF[ro] = v;
        if (outH) split2(v, outH + ro, outL + ro);
    }
}

// ---------------------------------------------------------------------------
// Selective scan
// ---------------------------------------------------------------------------
__global__ __launch_bounds__(256) void scan_kernel(
    const float* __restrict__ dt,
    const float* __restrict__ z,
    const float* __restrict__ xdbl,
    const float* __restrict__ A_log,
    const float* __restrict__ D_skip,
    __nv_bfloat16* __restrict__ y_hi, __nv_bfloat16* __restrict__ y_lo)
{
    const int gid = blockIdx.x * blockDim.x + threadIdx.x;
    const int d = gid >> 4;
    const int s = gid & 15;

    const float Aval = -expf(A_log[d * D_STATE + s]);
    const float Dv = D_skip[d];

    const float* Bp = xdbl + DT_RANK + s;
    const float* Cp = xdbl + DT_RANK + D_STATE + s;

    float h = 0.f;
    #pragma unroll 4
    for (int t = 0; t < LSEQ; t++) {
        const float dtv = dt[(size_t)t * D_INNER + d];
        const float zv  = z [(size_t)t * D_INNER + d];
        const float Bv  = Bp[(size_t)t * XPROJ_N];
        const float Cv  = Cp[(size_t)t * XPROJ_N];

        const float abar = __expf(dtv * Aval);
        h = fmaf(abar, h, dtv * zv * Bv);

        float p = h * Cv;
        p += __shfl_xor_sync(0xffffffffu, p, 8);
        p += __shfl_xor_sync(0xffffffffu, p, 4);
        p += __shfl_xor_sync(0xffffffffu, p, 2);
        p += __shfl_xor_sync(0xffffffffu, p, 1);
        if (s == 0) {
            float yv = p + Dv * zv;
            size_t o = (size_t)t * D_INNER + d;
            split2(yv, y_hi + o, y_lo + o);
        }
    }
}

// ---------------------------------------------------------------------------
// Launch
// ---------------------------------------------------------------------------
#define SMEM128 (2 * (2 * 128 * 128 + 2 * 128 * 128))   // 131072
#define SMEM64  (2 * (2 * 64 * 128 + 2 * 128 * 128))    // 98304

extern "C" void kernel_launch(void* const* d_in, const int* in_sizes, int n_in,
                              void* d_out, int out_size)
{
    const float* x        = (const float*)d_in[0];
    const float* w_norm1  = (const float*)d_in[1];
    const float* W_in     = (const float*)d_in[2];
    const float* W_gate   = (const float*)d_in[3];
    const float* W_xproj  = (const float*)d_in[4];
    const float* W_dt     = (const float*)d_in[5];
    const float* b_dt     = (const float*)d_in[6];
    const float* A_log    = (const float*)d_in[7];
    const float* D_skip   = (const float*)d_in[8];
    const float* W_out    = (const float*)d_in[9];
    const float* w_ffn    = (const float*)d_in[10];
    const float* W_up     = (const float*)d_in[11];
    const float* W_gate_f = (const float*)d_in[12];
    const float* W_down   = (const float*)d_in[13];
    float* out = (float*)d_out;

    float *p_lin1, *p_lin2, *p_xdbl, *p_dt, *p_x2, *p_up, *p_gate;
    cudaGetSymbolAddress((void**)&p_lin1, g_lin1);
    cudaGetSymbolAddress((void**)&p_lin2, g_lin2);
    cudaGetSymbolAddress((void**)&p_xdbl, g_xdbl);
    cudaGetSymbolAddress((void**)&p_dt,   g_dt);
    cudaGetSymbolAddress((void**)&p_x2,   g_x2);
    cudaGetSymbolAddress((void**)&p_up,   g_up);
    cudaGetSymbolAddress((void**)&p_gate, g_gate);

    __nv_bfloat16 *hH,*hL,*zH,*zL,*xdH,*xdL,*yH,*yL,*hfH,*hfL,*vH,*vL;
    cudaGetSymbolAddress((void**)&hH,  b_h_hi);  cudaGetSymbolAddress((void**)&hL,  b_h_lo);
    cudaGetSymbolAddress((void**)&zH,  b_z_hi);  cudaGetSymbolAddress((void**)&zL,  b_z_lo);
    cudaGetSymbolAddress((void**)&xdH, b_xd_hi); cudaGetSymbolAddress((void**)&xdL, b_xd_lo);
    cudaGetSymbolAddress((void**)&yH,  b_y_hi);  cudaGetSymbolAddress((void**)&yL,  b_y_lo);
    cudaGetSymbolAddress((void**)&hfH, b_hf_hi); cudaGetSymbolAddress((void**)&hfL, b_hf_lo);
    cudaGetSymbolAddress((void**)&vH,  b_v_hi);  cudaGetSymbolAddress((void**)&vL,  b_v_lo);

    __nv_bfloat16 *winH,*winL,*wgtH,*wgtL,*wxH,*wxL,*wdtH,*wdtL,*woH,*woL,*wuH,*wuL,*wgfH,*wgfL,*wdnH,*wdnL;
    cudaGetSymbolAddress((void**)&winH, w_in_hi);  cudaGetSymbolAddress((void**)&winL, w_in_lo);
    cudaGetSymbolAddress((void**)&wgtH, w_gt_hi);  cudaGetSymbolAddress((void**)&wgtL, w_gt_lo);
    cudaGetSymbolAddress((void**)&wxH,  w_x_hi);   cudaGetSymbolAddress((void**)&wxL,  w_x_lo);
    cudaGetSymbolAddress((void**)&wdtH, w_dt_hi);  cudaGetSymbolAddress((void**)&wdtL, w_dt_lo);
    cudaGetSymbolAddress((void**)&woH,  w_out_hi); cudaGetSymbolAddress((void**)&woL,  w_out_lo);
    cudaGetSymbolAddress((void**)&wuH,  w_up_hi);  cudaGetSymbolAddress((void**)&wuL,  w_up_lo);
    cudaGetSymbolAddress((void**)&wgfH, w_gf_hi);  cudaGetSymbolAddress((void**)&wgfL, w_gf_lo);
    cudaGetSymbolAddress((void**)&wdnH, w_dn_hi);  cudaGetSymbolAddress((void**)&wdnL, w_dn_lo);

    cudaFuncSetAttribute(gemm_bf3<128>, cudaFuncAttributeMaxDynamicSharedMemorySize, SMEM128);
    cudaFuncSetAttribute(gemm_bf3<64>,  cudaFuncAttributeMaxDynamicSharedMemorySize, SMEM64);

    const dim3 blk(256);
    #define SPLIT(src, hi, lo, n) split_kernel<<<((n)/4 + 255) / 256, blk>>>(src, hi, lo, (n)/4)

    SPLIT(W_in,     winH, winL, D_INNER * D_MODEL);
    SPLIT(W_gate,   wgtH, wgtL, D_INNER * D_MODEL);
    SPLIT(W_xproj,  wxH,  wxL,  XPROJ_N * D_INNER);
    split_wdt_kernel<<<(D_INNER * KDT_PAD + 255) / 256, blk>>>(W_dt, wdtH, wdtL);
    SPLIT(W_out,    woH,  woL,  D_MODEL * D_INNER);
    SPLIT(W_up,     wuH,  wuL,  H_FFN * D_MODEL);
    SPLIT(W_gate_f, wgfH, wgfL, H_FFN * D_MODEL);
    SPLIT(W_down,   wdnH, wdnL, D_MODEL * H_FFN);

    // 1) h = rmsnorm(x)
    rmsnorm_split_kernel<<<LSEQ, blk>>>(x, w_norm1, hH, hL);

    // 2+3) lin1 = h @ W_in^T ; lin2 = h @ W_gate^T  (batched, raw fp32)
    gemm_bf3<128><<<dim3(D_INNER / 128, LSEQ / 128, 2), blk, SMEM128>>>(
        hH, hL, winH, winL, wgtH, wgtL, D_MODEL, D_INNER,
        p_lin1, p_lin2, nullptr, nullptr, nullptr, nullptr, 0);

    // z = lin1 * sigmoid(lin2) -> fp32 (in-place) + splits
    gate_split_kernel<<<(LSEQ * D_INNER / 4 + 255) / 256, blk>>>(
        p_lin1, p_lin2, zH, zL, LSEQ * D_INNER / 4);

    // 4) xdbl = z @ W_xproj^T (BM=64)
    gemm_bf3<64><<<dim3(XPROJ_N / 128, LSEQ / 64), blk, SMEM64>>>(
        zH, zL, wxH, wxL, nullptr, nullptr, D_INNER, XPROJ_N,
        p_xdbl, nullptr, xdH, xdL, nullptr, nullptr, 0);

    // 5) dt = softplus(xdbl @ W_dt_pad^T + b_dt)
    gemm_bf3<128><<<dim3(D_INNER / 128, LSEQ / 128), blk, SMEM128>>>(
        xdH, xdL, wdtH, wdtL, nullptr, nullptr, KDT_PAD, D_INNER,
        p_dt, nullptr, nullptr, nullptr, nullptr, b_dt, 1);

    // 6) scan
    scan_kernel<<<(D_INNER * D_STATE) / 256, blk>>>(p_dt, p_lin1, p_xdbl,
                                                    A_log, D_skip, yH, yL);

    // 7) x2 = x + y @ W_out^T (BM=64)
    gemm_bf3<64><<<dim3(D_MODEL / 128, LSEQ / 64), blk, SMEM64>>>(
        yH, yL, woH, woL, nullptr, nullptr, D_INNER, D_MODEL,
        p_x2, nullptr, nullptr, nullptr, x, nullptr, 3);

    // 8) hf = rmsnorm(x2)
    rmsnorm_split_kernel<<<LSEQ, blk>>>(p_x2, w_ffn, hfH, hfL);

    // 9+10a) up = hf @ W_up^T ; gate = hf @ W_gate_ffn^T (batched raw)
    gemm_bf3<128><<<dim3(H_FFN / 128, LSEQ / 128, 2), blk, SMEM128>>>(
        hfH, hfL, wuH, wuL, wgfH, wgfL, D_MODEL, H_FFN,
        p_up, p_gate, nullptr, nullptr, nullptr, nullptr, 0);

    // 10b) v = silu(gate) * up -> splits
    silu_mul_split_kernel<<<(LSEQ * H_FFN / 4 + 255) / 256, blk>>>(
        p_up, p_gate, vH, vL, LSEQ * H_FFN / 4);

    // 11) out = x2 + v @ W_down^T (BM=64)
    gemm_bf3<64><<<dim3(D_MODEL / 128, LSEQ / 64), blk, SMEM64>>>(
        vH, vL, wdnH, wdnL, nullptr, nullptr, H_FFN, D_MODEL,
        out, nullptr, nullptr, nullptr, p_x2, nullptr, 3);
}

// round 5
// speedup vs baseline: 2.3610x; 1.2247x over previous
#include <cuda_runtime.h>
#include <cuda_fp16.h>
#include <math.h>
#include <stdint.h>

// ---------------------------------------------------------------------------
// Problem dims
// ---------------------------------------------------------------------------
#define D_MODEL 768
#define D_INNER 1536
#define D_STATE 16
#define DT_RANK 96
#define H_FFN   2048
#define LSEQ    2048
#define XPROJ_N 128
#define KDT_PAD 128

// ---------------------------------------------------------------------------
// Scratch
// ---------------------------------------------------------------------------
__device__ float g_lin1[LSEQ * D_INNER];   // raw in-proj, then z (in-place)
__device__ float g_lin2[LSEQ * D_INNER];   // raw gate-proj
__device__ float g_xdbl[LSEQ * XPROJ_N];
__device__ float g_dt  [LSEQ * D_INNER];
__device__ float g_x2  [LSEQ * D_MODEL];
__device__ float g_up  [LSEQ * H_FFN];
__device__ float g_gate[LSEQ * H_FFN];

// fp16 activation splits (hi/lo)
__device__ __half a_h_hi [LSEQ * D_MODEL],  a_h_lo [LSEQ * D_MODEL];
__device__ __half a_z_hi [LSEQ * D_INNER],  a_z_lo [LSEQ * D_INNER];
__device__ __half a_xd_hi[LSEQ * XPROJ_N],  a_xd_lo[LSEQ * XPROJ_N];
__device__ __half a_y_hi [LSEQ * D_INNER],  a_y_lo [LSEQ * D_INNER];
__device__ __half a_hf_hi[LSEQ * D_MODEL],  a_hf_lo[LSEQ * D_MODEL];
__device__ __half a_v_hi [LSEQ * H_FFN],    a_v_lo [LSEQ * H_FFN];

// fp16 weights (single precision term)
__device__ __half w_in_h [D_INNER * D_MODEL];
__device__ __half w_gt_h [D_INNER * D_MODEL];
__device__ __half w_x_h  [XPROJ_N * D_INNER];
__device__ __half w_dt_h [D_INNER * KDT_PAD];
__device__ __half w_out_h[D_MODEL * D_INNER];
__device__ __half w_up_h [H_FFN * D_MODEL];
__device__ __half w_gf_h [H_FFN * D_MODEL];
__device__ __half w_dn_h [D_MODEL * H_FFN];

static __device__ __forceinline__ void split2h(float v, __half* hi, __half* lo) {
    __half h = __float2half_rn(v);
    *hi = h;
    *lo = __float2half_rn(v - __half2float(h));
}

static __device__ __forceinline__ uint32_t smem_u32(const void* p) {
    uint32_t a;
    asm("{ .reg .u64 t; cvta.to.shared.u64 t, %1; cvt.u32.u64 %0, t; }"
        : "=r"(a) : "l"(p));
    return a;
}

#define SW128(off) ((off) ^ (((off) >> 3) & 0x70))

#define LDSM4(r, addr)                                                         \
    asm volatile("ldmatrix.sync.aligned.m8n8.x4.shared.b16 {%0,%1,%2,%3}, [%4];" \
        : "=r"((r)[0]), "=r"((r)[1]), "=r"((r)[2]), "=r"((r)[3]) : "r"(addr))

#define MMA16816(c, a, b0, b1)                                                 \
    asm volatile("mma.sync.aligned.m16n8k16.row.col.f32.f16.f16.f32 "          \
        "{%0,%1,%2,%3}, {%4,%5,%6,%7}, {%8,%9}, {%0,%1,%2,%3};"                \
        : "+f"((c)[0]), "+f"((c)[1]), "+f"((c)[2]), "+f"((c)[3])               \
        : "r"((a)[0]), "r"((a)[1]), "r"((a)[2]), "r"((a)[3]), "r"(b0), "r"(b1))

#define CP_ASYNC16(sa, ga)                                                     \
    asm volatile("{ .reg .u64 g; cvta.to.global.u64 g, %1; "                   \
                 "cp.async.cg.shared.global [%0], [g], 16; }"                  \
                 :: "r"(sa), "l"(ga))
#define CP_COMMIT()  asm volatile("cp.async.commit_group;" ::: "memory")
#define CP_WAIT1()   asm volatile("cp.async.wait_group 1;" ::: "memory")

// ---------------------------------------------------------------------------
// Weight fp16 convert + misc elementwise
// ---------------------------------------------------------------------------
__global__ void w16_kernel(const float* __restrict__ src,
                           __half* __restrict__ dst, int n4)
{
    int i = blockIdx.x * blockDim.x + threadIdx.x;
    if (i < n4) {
        float4 v = reinterpret_cast<const float4*>(src)[i];
        __half2* d = reinterpret_cast<__half2*>(dst) + i * 2;
        d[0] = __floats2half2_rn(v.x, v.y);
        d[1] = __floats2half2_rn(v.z, v.w);
    }
}

__global__ void w16_wdt_kernel(const float* __restrict__ src,
                               __half* __restrict__ dst)
{
    int i = blockIdx.x * blockDim.x + threadIdx.x;
    if (i < D_INNER * KDT_PAD) {
        int r = i / KDT_PAD, c = i % KDT_PAD;
        float v = (c < DT_RANK) ? src[r * DT_RANK + c] : 0.f;
        dst[i] = __float2half_rn(v);
    }
}

// z = lin1 * sigmoid(lin2); fp32 in-place over lin1 + fp16 splits
__global__ void gate_split_kernel(float* __restrict__ lin1,
                                  const float* __restrict__ lin2,
                                  __half* __restrict__ zH,
                                  __half* __restrict__ zL, int n4)
{
    int i = blockIdx.x * blockDim.x + threadIdx.x;
    if (i < n4) {
        float4 a = reinterpret_cast<float4*>(lin1)[i];
        float4 g = reinterpret_cast<const float4*>(lin2)[i];
        a.x *= 1.f / (1.f + __expf(-g.x));
        a.y *= 1.f / (1.f + __expf(-g.y));
        a.z *= 1.f / (1.f + __expf(-g.z));
        a.w *= 1.f / (1.f + __expf(-g.w));
        reinterpret_cast<float4*>(lin1)[i] = a;
        int b = i * 4;
        split2h(a.x, zH + b + 0, zL + b + 0);
        split2h(a.y, zH + b + 1, zL + b + 1);
        split2h(a.z, zH + b + 2, zL + b + 2);
        split2h(a.w, zH + b + 3, zL + b + 3);
    }
}

// v = silu(gate) * up -> fp16 splits
__global__ void silu_mul_split_kernel(const float* __restrict__ up,
                                      const float* __restrict__ gate,
                                      __half* __restrict__ vH,
                                      __half* __restrict__ vL, int n4)
{
    int i = blockIdx.x * blockDim.x + threadIdx.x;
    if (i < n4) {
        float4 u = reinterpret_cast<const float4*>(up)[i];
        float4 g = reinterpret_cast<const float4*>(gate)[i];
        float4 v;
        v.x = g.x / (1.f + __expf(-g.x)) * u.x;
        v.y = g.y / (1.f + __expf(-g.y)) * u.y;
        v.z = g.z / (1.f + __expf(-g.z)) * u.z;
        v.w = g.w / (1.f + __expf(-g.w)) * u.w;
        int b = i * 4;
        split2h(v.x, vH + b + 0, vL + b + 0);
        split2h(v.y, vH + b + 1, vL + b + 1);
        split2h(v.z, vH + b + 2, vL + b + 2);
        split2h(v.w, vH + b + 3, vL + b + 3);
    }
}

// fp32 -> fp16 hi/lo split (for xdbl after split-K)
__global__ void split_f32_kernel(const float* __restrict__ src,
                                 __half* __restrict__ hi,
                                 __half* __restrict__ lo, int n4)
{
    int i = blockIdx.x * blockDim.x + threadIdx.x;
    if (i < n4) {
        float4 v = reinterpret_cast<const float4*>(src)[i];
        int b = i * 4;
        split2h(v.x, hi + b + 0, lo + b + 0);
        split2h(v.y, hi + b + 1, lo + b + 1);
        split2h(v.z, hi + b + 2, lo + b + 2);
        split2h(v.w, hi + b + 3, lo + b + 3);
    }
}

// ---------------------------------------------------------------------------
// RMSNorm -> fp16 splits
// ---------------------------------------------------------------------------
__global__ __launch_bounds__(256) void rmsnorm_split_kernel(
    const float* __restrict__ x, const float* __restrict__ w,
    __half* __restrict__ hi, __half* __restrict__ lo)
{
    const int t = blockIdx.x;
    const float* xr = x + (size_t)t * D_MODEL;

    float ss = 0.f;
    for (int i = threadIdx.x; i < D_MODEL; i += 256) {
        float v = xr[i];
        ss = fmaf(v, v, ss);
    }
    #pragma unroll
    for (int o = 16; o > 0; o >>= 1) ss += __shfl_xor_sync(0xffffffffu, ss, o);

    __shared__ float sh[8];
    __shared__ float s_rs;
    const int lane = threadIdx.x & 31, wid = threadIdx.x >> 5;
    if (lane == 0) sh[wid] = ss;
    __syncthreads();
    if (threadIdx.x == 0) {
        float tot = 0.f;
        #pragma unroll
        for (int i = 0; i < 8; i++) tot += sh[i];
        s_rs = rsqrtf(tot * (1.0f / D_MODEL) + 1e-6f);
    }
    __syncthreads();
    const float rs = s_rs;
    for (int i = threadIdx.x; i < D_MODEL; i += 256) {
        float v = xr[i] * rs * w[i];
        size_t o = (size_t)t * D_MODEL + i;
        split2h(v, hi + o, lo + o);
    }
}

// ---------------------------------------------------------------------------
// fp16 2-term GEMM on mma.sync: C[M,N] = f(A[M,K] @ B[N,K]^T)
//   acc = Ah*Bh + Al*Bh (A split hi/lo fp16, B single fp16), fp32 accumulate.
//   BM in {128, 64}; BN=128, KC=64, 256 threads.
//   op: 0 none | 1 bias+softplus | 3 acc+aux | 5 split-K atomicAdd
//   op!=5: gridDim.z==2 batches a second (B2, out2) GEMM sharing A.
//   op==5: gridDim.z = K-splits; partial sums atomically added to outF.
// ---------------------------------------------------------------------------
template<int BM>
__global__ __launch_bounds__(256) void gemm_h2(
    const __half* __restrict__ Ah, const __half* __restrict__ Al,
    const __half* __restrict__ Bh_, const __half* __restrict__ B2h,
    int K, int N,
    float* __restrict__ outF_, float* __restrict__ out2F,
    __half* __restrict__ outH, __half* __restrict__ outL,
    const float* __restrict__ aux, const float* __restrict__ bias, int op)
{
    constexpr int WN  = (BM == 128) ? 2 : 4;
    constexpr int NT  = 128 / WN / 8;            // 8 or 4
    constexpr int ATB = BM * 128;                // bytes: BM rows x 64 halves
    constexpr int BTB = 128 * 128;
    constexpr int STAGE_B = 2 * ATB + BTB;

    const bool batched2 = (op != 5) && (blockIdx.z != 0);
    const __half* Bh = batched2 ? B2h : Bh_;
    float* outF = batched2 ? out2F : outF_;

    int k_begin = 0, KL = K;
    if (op == 5) { KL = K / gridDim.z; k_begin = blockIdx.z * KL; }

    extern __shared__ char smem[];
    const uint32_t sb = smem_u32(smem);
    const int tid  = threadIdx.x;
    const int lane = tid & 31;
    const int warp = tid >> 5;
    const int m0 = blockIdx.y * BM;
    const int n0 = blockIdx.x * 128;
    const int wm0 = (warp / WN) * 32;
    const int wn0 = (warp % WN) * (128 / WN);

    const int nch = KL >> 6;

    float acc[2][NT][4];
    #pragma unroll
    for (int mt = 0; mt < 2; mt++)
        #pragma unroll
        for (int nt = 0; nt < NT; nt++)
            #pragma unroll
            for (int r = 0; r < 4; r++) acc[mt][nt][r] = 0.f;

    auto load_stage = [&](int s, int ci) {
        const int k0 = k_begin + (ci << 6);
        const uint32_t sbase = sb + s * STAGE_B;
        #pragma unroll
        for (int arr = 0; arr < 3; arr++) {
            const __half* src = (arr == 0) ? Ah : (arr == 1) ? Al : Bh;
            const int r0 = (arr < 2) ? m0 : n0;
            const int nvec = ((arr < 2) ? BM : 128) * 8;
            const uint32_t abase = sbase + ((arr == 0) ? 0 : (arr == 1) ? ATB : 2 * ATB);
            #pragma unroll
            for (int jj = 0; jj < nvec / 256; jj++) {
                const int idx = jj * 256 + tid;
                const int row = idx >> 3;
                const int c16 = idx & 7;
                const __half* g = src + (size_t)(r0 + row) * K + k0 + c16 * 8;
                const uint32_t sa = abase + SW128((uint32_t)(row * 128 + c16 * 16));
                CP_ASYNC16(sa, g);
            }
        }
    };

    const int arow = ((lane >> 3) & 1) * 8 + (lane & 7);
    const int akb  = (lane >> 4) * 16;
    const int brow = ((lane >> 4) & 1) * 8 + (lane & 7);
    const int bkb  = ((lane >> 3) & 1) * 16;

    auto compute = [&](int s) {
        const uint32_t sA_h = sb + s * STAGE_B;
        const uint32_t sA_l = sA_h + ATB;
        const uint32_t sB_h = sA_h + 2 * ATB;
        #pragma unroll
        for (int ks = 0; ks < 4; ks++) {
            uint32_t a_h[2][4], a_l[2][4], b_h[NT / 2][4];
            #pragma unroll
            for (int mt = 0; mt < 2; mt++) {
                const uint32_t off = SW128(
                    (uint32_t)((wm0 + mt * 16 + arow) * 128 + ks * 32 + akb));
                LDSM4(a_h[mt], sA_h + off);
                LDSM4(a_l[mt], sA_l + off);
            }
            #pragma unroll
            for (int j = 0; j < NT / 2; j++) {
                const uint32_t off = SW128(
                    (uint32_t)((wn0 + j * 16 + brow) * 128 + ks * 32 + bkb));
                LDSM4(b_h[j], sB_h + off);
            }
            #pragma unroll
            for (int mt = 0; mt < 2; mt++)
                #pragma unroll
                for (int nt = 0; nt < NT; nt++) {
                    const uint32_t bh0 = b_h[nt >> 1][(nt & 1) * 2];
                    const uint32_t bh1 = b_h[nt >> 1][(nt & 1) * 2 + 1];
                    MMA16816(acc[mt][nt], a_h[mt], bh0, bh1);
                    MMA16816(acc[mt][nt], a_l[mt], bh0, bh1);
                }
        }
    };

    load_stage(0, 0); CP_COMMIT();
    load_stage(1, 1); CP_COMMIT();
    for (int i = 0; i < nch; i++) {
        CP_WAIT1();
        __syncthreads();
        compute(i & 1);
        __syncthreads();
        if (i + 2 < nch) load_stage(i & 1, i + 2);
        CP_COMMIT();
    }
    __syncthreads();

    // epilogue via smem for coalesced stores
    float* smC = reinterpret_cast<float*>(smem);   // [BM][132]
    #pragma unroll
    for (int mt = 0; mt < 2; mt++)
        #pragma unroll
        for (int nt = 0; nt < NT; nt++) {
            const int row = wm0 + mt * 16 + (lane >> 2);
            const int col = wn0 + nt * 8 + (lane & 3) * 2;
            *reinterpret_cast<float2*>(&smC[row * 132 + col]) =
                make_float2(acc[mt][nt][0], acc[mt][nt][1]);
            *reinterpret_cast<float2*>(&smC[(row + 8) * 132 + col]) =
                make_float2(acc[mt][nt][2], acc[mt][nt][3]);
        }
    __syncthreads();

    #pragma unroll 4
    for (int e = tid; e < BM * 128; e += 256) {
        const int row = e >> 7, col = e & 127;
        float v = smC[row * 132 + col];
        const size_t ro = (size_t)(m0 + row) * N + (n0 + col);
        if (op == 1) {
            v += bias[n0 + col];
            v = (v > 20.f) ? v : log1pf(__expf(v));
        } else if (op == 3) {
            v += aux[ro];
        } else if (op == 5) {
            atomicAdd(&outF[ro], v);
            continue;
        }
        if (outF) outF[ro] = v;
        if (outH) split2h(v, outH + ro, outL + ro);
    }
}

// ---------------------------------------------------------------------------
// Selective scan (128-thread blocks -> 192 CTAs)
// ---------------------------------------------------------------------------
__global__ __launch_bounds__(128) void scan_kernel(
    const float* __restrict__ dt,
    const float* __restrict__ z,
    const float* __restrict__ xdbl,
    const float* __restrict__ A_log,
    const float* __restrict__ D_skip,
    __half* __restrict__ y_hi, __half* __restrict__ y_lo)
{
    const int gid = blockIdx.x * blockDim.x + threadIdx.x;
    const int d = gid >> 4;
    const int s = gid & 15;

    const float Aval = -expf(A_log[d * D_STATE + s]);
    const float Dv = D_skip[d];

    const float* Bp = xdbl + DT_RANK + s;
    const float* Cp = xdbl + DT_RANK + D_STATE + s;

    float h = 0.f;
    #pragma unroll 4
    for (int t = 0; t < LSEQ; t++) {
        const float dtv = dt[(size_t)t * D_INNER + d];
        const float zv  = z [(size_t)t * D_INNER + d];
        const float Bv  = Bp[(size_t)t * XPROJ_N];
        const float Cv  = Cp[(size_t)t * XPROJ_N];

        const float abar = __expf(dtv * Aval);
        h = fmaf(abar, h, dtv * zv * Bv);

        float p = h * Cv;
        p += __shfl_xor_sync(0xffffffffu, p, 8);
        p += __shfl_xor_sync(0xffffffffu, p, 4);
        p += __shfl_xor_sync(0xffffffffu, p, 2);
        p += __shfl_xor_sync(0xffffffffu, p, 1);
        if (s == 0) {
            float yv = p + Dv * zv;
            size_t o = (size_t)t * D_INNER + d;
            split2h(yv, y_hi + o, y_lo + o);
        }
    }
}

// ---------------------------------------------------------------------------
// Launch
// ---------------------------------------------------------------------------
#define SMEM128 (2 * (2 * 128 * 128 + 128 * 128))   // 98304
#define SMEM64  (2 * (2 * 64 * 128 + 128 * 128))    // 65536

extern "C" void kernel_launch(void* const* d_in, const int* in_sizes, int n_in,
                              void* d_out, int out_size)
{
    const float* x        = (const float*)d_in[0];
    const float* w_norm1  = (const float*)d_in[1];
    const float* W_in     = (const float*)d_in[2];
    const float* W_gate   = (const float*)d_in[3];
    const float* W_xproj  = (const float*)d_in[4];
    const float* W_dt     = (const float*)d_in[5];
    const float* b_dt     = (const float*)d_in[6];
    const float* A_log    = (const float*)d_in[7];
    const float* D_skip   = (const float*)d_in[8];
    const float* W_out    = (const float*)d_in[9];
    const float* w_ffn    = (const float*)d_in[10];
    const float* W_up     = (const float*)d_in[11];
    const float* W_gate_f = (const float*)d_in[12];
    const float* W_down   = (const float*)d_in[13];
    float* out = (float*)d_out;

    float *p_lin1, *p_lin2, *p_xdbl, *p_dt, *p_x2, *p_up, *p_gate;
    cudaGetSymbolAddress((void**)&p_lin1, g_lin1);
    cudaGetSymbolAddress((void**)&p_lin2, g_lin2);
    cudaGetSymbolAddress((void**)&p_xdbl, g_xdbl);
    cudaGetSymbolAddress((void**)&p_dt,   g_dt);
    cudaGetSymbolAddress((void**)&p_x2,   g_x2);
    cudaGetSymbolAddress((void**)&p_up,   g_up);
    cudaGetSymbolAddress((void**)&p_gate, g_gate);

    __half *hH,*hL,*zH,*zL,*xdH,*xdL,*yH,*yL,*hfH,*hfL,*vH,*vL;
    cudaGetSymbolAddress((void**)&hH,  a_h_hi);  cudaGetSymbolAddress((void**)&hL,  a_h_lo);
    cudaGetSymbolAddress((void**)&zH,  a_z_hi);  cudaGetSymbolAddress((void**)&zL,  a_z_lo);
    cudaGetSymbolAddress((void**)&xdH, a_xd_hi); cudaGetSymbolAddress((void**)&xdL, a_xd_lo);
    cudaGetSymbolAddress((void**)&yH,  a_y_hi);  cudaGetSymbolAddress((void**)&yL,  a_y_lo);
    cudaGetSymbolAddress((void**)&hfH, a_hf_hi); cudaGetSymbolAddress((void**)&hfL, a_hf_lo);
    cudaGetSymbolAddress((void**)&vH,  a_v_hi);  cudaGetSymbolAddress((void**)&vL,  a_v_lo);

    __half *winH,*wgtH,*wxH,*wdtH,*woH,*wuH,*wgfH,*wdnH;
    cudaGetSymbolAddress((void**)&winH, w_in_h);
    cudaGetSymbolAddress((void**)&wgtH, w_gt_h);
    cudaGetSymbolAddress((void**)&wxH,  w_x_h);
    cudaGetSymbolAddress((void**)&wdtH, w_dt_h);
    cudaGetSymbolAddress((void**)&woH,  w_out_h);
    cudaGetSymbolAddress((void**)&wuH,  w_up_h);
    cudaGetSymbolAddress((void**)&wgfH, w_gf_h);
    cudaGetSymbolAddress((void**)&wdnH, w_dn_h);

    cudaFuncSetAttribute(gemm_h2<128>, cudaFuncAttributeMaxDynamicSharedMemorySize, SMEM128);
    cudaFuncSetAttribute(gemm_h2<64>,  cudaFuncAttributeMaxDynamicSharedMemorySize, SMEM64);

    const dim3 blk(256);
    #define W16(src, dst, n) w16_kernel<<<((n)/4 + 255) / 256, blk>>>(src, dst, (n)/4)

    W16(W_in,     winH, D_INNER * D_MODEL);
    W16(W_gate,   wgtH, D_INNER * D_MODEL);
    W16(W_xproj,  wxH,  XPROJ_N * D_INNER);
    w16_wdt_kernel<<<(D_INNER * KDT_PAD + 255) / 256, blk>>>(W_dt, wdtH);
    W16(W_out,    woH,  D_MODEL * D_INNER);
    W16(W_up,     wuH,  H_FFN * D_MODEL);
    W16(W_gate_f, wgfH, H_FFN * D_MODEL);
    W16(W_down,   wdnH, D_MODEL * H_FFN);

    // 1) h = rmsnorm(x)
    rmsnorm_split_kernel<<<LSEQ, blk>>>(x, w_norm1, hH, hL);

    // 2+3) lin1 = h @ W_in^T ; lin2 = h @ W_gate^T  (batched raw fp32)
    gemm_h2<128><<<dim3(D_INNER / 128, LSEQ / 128, 2), blk, SMEM128>>>(
        hH, hL, winH, wgtH, D_MODEL, D_INNER,
        p_lin1, p_lin2, nullptr, nullptr, nullptr, nullptr, 0);

    // z = lin1 * sigmoid(lin2)
    gate_split_kernel<<<(LSEQ * D_INNER / 4 + 255) / 256, blk>>>(
        p_lin1, p_lin2, zH, zL, LSEQ * D_INNER / 4);

    // 4) xdbl = z @ W_xproj^T  (split-K = 4, atomic accumulate)
    cudaMemsetAsync(p_xdbl, 0, (size_t)LSEQ * XPROJ_N * sizeof(float));
    gemm_h2<64><<<dim3(XPROJ_N / 128, LSEQ / 64, 4), blk, SMEM64>>>(
        zH, zL, wxH, nullptr, D_INNER, XPROJ_N,
        p_xdbl, nullptr, nullptr, nullptr, nullptr, nullptr, 5);
    split_f32_kernel<<<(LSEQ * XPROJ_N / 4 + 255) / 256, blk>>>(
        p_xdbl, xdH, xdL, LSEQ * XPROJ_N / 4);

    // 5) dt = softplus(xdbl @ W_dt_pad^T + b_dt)
    gemm_h2<128><<<dim3(D_INNER / 128, LSEQ / 128), blk, SMEM128>>>(
        xdH, xdL, wdtH, nullptr, KDT_PAD, D_INNER,
        p_dt, nullptr, nullptr, nullptr, nullptr, b_dt, 1);

    // 6) scan
    scan_kernel<<<(D_INNER * D_STATE) / 128, dim3(128)>>>(
        p_dt, p_lin1, p_xdbl, A_log, D_skip, yH, yL);

    // 7) x2 = x + y @ W_out^T
    gemm_h2<64><<<dim3(D_MODEL / 128, LSEQ / 64), blk, SMEM64>>>(
        yH, yL, woH, nullptr, D_INNER, D_MODEL,
        p_x2, nullptr, nullptr, nullptr, x, nullptr, 3);

    // 8) hf = rmsnorm(x2)
    rmsnorm_split_kernel<<<LSEQ, blk>>>(p_x2, w_ffn, hfH, hfL);

    // 9+10a) up / gate (batched raw)
    gemm_h2<128><<<dim3(H_FFN / 128, LSEQ / 128, 2), blk, SMEM128>>>(
        hfH, hfL, wuH, wgfH, D_MODEL, H_FFN,
        p_up, p_gate, nullptr, nullptr, nullptr, nullptr, 0);

    // 10b) v = silu(gate) * up
    silu_mul_split_kernel<<<(LSEQ * H_FFN / 4 + 255) / 256, blk>>>(
        p_up, p_gate, vH, vL, LSEQ * H_FFN / 4);

    // 11) out = x2 + v @ W_down^T
    gemm_h2<64><<<dim3(D_MODEL / 128, LSEQ / 64), blk, SMEM64>>>(
        vH, vL, wdnH, nullptr, H_FFN, D_MODEL,
        out, nullptr, nullptr, nullptr, p_x2, nullptr, 3);
}

// round 6
// speedup vs baseline: 2.9827x; 1.2633x over previous
#include <cuda_runtime.h>
#include <cuda_fp16.h>
#include <math.h>
#include <stdint.h>

// ---------------------------------------------------------------------------
// Problem dims
// ---------------------------------------------------------------------------
#define D_MODEL 768
#define D_INNER 1536
#define D_STATE 16
#define DT_RANK 96
#define H_FFN   2048
#define LSEQ    2048
#define XPROJ_N 128
#define KDT_PAD 128

// ---------------------------------------------------------------------------
// Scratch
// ---------------------------------------------------------------------------
__device__ float g_lin1[LSEQ * D_INNER];   // raw in-proj, then z (in-place)
__device__ float g_lin2[LSEQ * D_INNER];   // raw gate-proj
__device__ float g_xdbl[LSEQ * XPROJ_N];
__device__ float g_dt  [LSEQ * D_INNER];
__device__ float g_x2  [LSEQ * D_MODEL];
__device__ float g_up  [LSEQ * H_FFN];
__device__ float g_gate[LSEQ * H_FFN];

// fp16 activations
__device__ __half a_h  [LSEQ * D_MODEL];
__device__ __half a_z  [LSEQ * D_INNER];
__device__ __half a_xd [LSEQ * XPROJ_N];
__device__ __half a_y  [LSEQ * D_INNER];
__device__ __half a_hf [LSEQ * D_MODEL];
__device__ __half a_v  [LSEQ * H_FFN];

// fp16 weights
__device__ __half w_in_h [D_INNER * D_MODEL];
__device__ __half w_gt_h [D_INNER * D_MODEL];
__device__ __half w_x_h  [XPROJ_N * D_INNER];
__device__ __half w_dt_h [D_INNER * KDT_PAD];
__device__ __half w_out_h[D_MODEL * D_INNER];
__device__ __half w_up_h [H_FFN * D_MODEL];
__device__ __half w_gf_h [H_FFN * D_MODEL];
__device__ __half w_dn_h [D_MODEL * H_FFN];

static __device__ __forceinline__ uint32_t smem_u32(const void* p) {
    uint32_t a;
    asm("{ .reg .u64 t; cvta.to.shared.u64 t, %1; cvt.u32.u64 %0, t; }"
        : "=r"(a) : "l"(p));
    return a;
}

#define SW128(off) ((off) ^ (((off) >> 3) & 0x70))

#define LDSM4(r, addr)                                                         \
    asm volatile("ldmatrix.sync.aligned.m8n8.x4.shared.b16 {%0,%1,%2,%3}, [%4];" \
        : "=r"((r)[0]), "=r"((r)[1]), "=r"((r)[2]), "=r"((r)[3]) : "r"(addr))

#define MMA16816(c, a, b0, b1)                                                 \
    asm volatile("mma.sync.aligned.m16n8k16.row.col.f32.f16.f16.f32 "          \
        "{%0,%1,%2,%3}, {%4,%5,%6,%7}, {%8,%9}, {%0,%1,%2,%3};"                \
        : "+f"((c)[0]), "+f"((c)[1]), "+f"((c)[2]), "+f"((c)[3])               \
        : "r"((a)[0]), "r"((a)[1]), "r"((a)[2]), "r"((a)[3]), "r"(b0), "r"(b1))

#define CP_ASYNC16(sa, ga)                                                     \
    asm volatile("{ .reg .u64 g; cvta.to.global.u64 g, %1; "                   \
                 "cp.async.cg.shared.global [%0], [g], 16; }"                  \
                 :: "r"(sa), "l"(ga))
#define CP_COMMIT()  asm volatile("cp.async.commit_group;" ::: "memory")
#define CP_WAIT1()   asm volatile("cp.async.wait_group 1;" ::: "memory")

// ---------------------------------------------------------------------------
// All-weights fp32->fp16 convert, one launch, compile-time segments (float4)
// ---------------------------------------------------------------------------
#define N_IN  (D_INNER * D_MODEL)
#define N_X   (XPROJ_N * D_INNER)
#define N_OUT (D_MODEL * D_INNER)
#define N_UP  (H_FFN * D_MODEL)
#define N_DN  (D_MODEL * H_FFN)
#define Q4(n) ((n) / 4)
#define SEG0 Q4(N_IN)
#define SEG1 (SEG0 + Q4(N_IN))
#define SEG2 (SEG1 + Q4(N_X))
#define SEG3 (SEG2 + Q4(N_OUT))
#define SEG4 (SEG3 + Q4(N_UP))
#define SEG5 (SEG4 + Q4(N_UP))
#define SEG6 (SEG5 + Q4(N_DN))

__global__ void w16_all_kernel(
    const float* __restrict__ sin,  __half* __restrict__ din,
    const float* __restrict__ sgt,  __half* __restrict__ dgt,
    const float* __restrict__ sx,   __half* __restrict__ dx,
    const float* __restrict__ sout, __half* __restrict__ dout,
    const float* __restrict__ sup,  __half* __restrict__ dup,
    const float* __restrict__ sgf,  __half* __restrict__ dgf,
    const float* __restrict__ sdn,  __half* __restrict__ ddn)
{
    int i = blockIdx.x * blockDim.x + threadIdx.x;
    if (i >= SEG6) return;
    const float* s; __half* d; int b;
    if      (i < SEG0) { s = sin;  d = din;  b = i; }
    else if (i < SEG1) { s = sgt;  d = dgt;  b = i - SEG0; }
    else if (i < SEG2) { s = sx;   d = dx;   b = i - SEG1; }
    else if (i < SEG3) { s = sout; d = dout; b = i - SEG2; }
    else if (i < SEG4) { s = sup;  d = dup;  b = i - SEG3; }
    else if (i < SEG5) { s = sgf;  d = dgf;  b = i - SEG4; }
    else               { s = sdn;  d = ddn;  b = i - SEG5; }
    float4 v = reinterpret_cast<const float4*>(s)[b];
    __half2* o = reinterpret_cast<__half2*>(d) + b * 2;
    o[0] = __floats2half2_rn(v.x, v.y);
    o[1] = __floats2half2_rn(v.z, v.w);
}

__global__ void w16_wdt_kernel(const float* __restrict__ src,
                               __half* __restrict__ dst)
{
    int i = blockIdx.x * blockDim.x + threadIdx.x;
    if (i < D_INNER * KDT_PAD) {
        int r = i / KDT_PAD, c = i % KDT_PAD;
        float v = (c < DT_RANK) ? src[r * DT_RANK + c] : 0.f;
        dst[i] = __float2half_rn(v);
    }
}

// ---------------------------------------------------------------------------
// Elementwise
// ---------------------------------------------------------------------------
// z = lin1 * sigmoid(lin2); fp32 in-place + fp16
__global__ void gate_kernel(float* __restrict__ lin1,
                            const float* __restrict__ lin2,
                            __half* __restrict__ zh, int n4)
{
    int i = blockIdx.x * blockDim.x + threadIdx.x;
    if (i < n4) {
        float4 a = reinterpret_cast<float4*>(lin1)[i];
        float4 g = reinterpret_cast<const float4*>(lin2)[i];
        a.x *= 1.f / (1.f + __expf(-g.x));
        a.y *= 1.f / (1.f + __expf(-g.y));
        a.z *= 1.f / (1.f + __expf(-g.z));
        a.w *= 1.f / (1.f + __expf(-g.w));
        reinterpret_cast<float4*>(lin1)[i] = a;
        __half2* o = reinterpret_cast<__half2*>(zh) + i * 2;
        o[0] = __floats2half2_rn(a.x, a.y);
        o[1] = __floats2half2_rn(a.z, a.w);
    }
}

// v = silu(gate) * up -> fp16
__global__ void silu_mul_kernel(const float* __restrict__ up,
                                const float* __restrict__ gate,
                                __half* __restrict__ vh, int n4)
{
    int i = blockIdx.x * blockDim.x + threadIdx.x;
    if (i < n4) {
        float4 u = reinterpret_cast<const float4*>(up)[i];
        float4 g = reinterpret_cast<const float4*>(gate)[i];
        float4 v;
        v.x = g.x / (1.f + __expf(-g.x)) * u.x;
        v.y = g.y / (1.f + __expf(-g.y)) * u.y;
        v.z = g.z / (1.f + __expf(-g.z)) * u.z;
        v.w = g.w / (1.f + __expf(-g.w)) * u.w;
        __half2* o = reinterpret_cast<__half2*>(vh) + i * 2;
        o[0] = __floats2half2_rn(v.x, v.y);
        o[1] = __floats2half2_rn(v.z, v.w);
    }
}

// fp32 -> fp16 (xdbl after split-K)
__global__ void cvt16_kernel(const float* __restrict__ src,
                             __half* __restrict__ dst, int n4)
{
    int i = blockIdx.x * blockDim.x + threadIdx.x;
    if (i < n4) {
        float4 v = reinterpret_cast<const float4*>(src)[i];
        __half2* o = reinterpret_cast<__half2*>(dst) + i * 2;
        o[0] = __floats2half2_rn(v.x, v.y);
        o[1] = __floats2half2_rn(v.z, v.w);
    }
}

// ---------------------------------------------------------------------------
// RMSNorm -> fp16
// ---------------------------------------------------------------------------
__global__ __launch_bounds__(256) void rmsnorm_kernel(
    const float* __restrict__ x, const float* __restrict__ w,
    __half* __restrict__ o16)
{
    const int t = blockIdx.x;
    const float* xr = x + (size_t)t * D_MODEL;

    float ss = 0.f;
    for (int i = threadIdx.x; i < D_MODEL; i += 256) {
        float v = xr[i];
        ss = fmaf(v, v, ss);
    }
    #pragma unroll
    for (int o = 16; o > 0; o >>= 1) ss += __shfl_xor_sync(0xffffffffu, ss, o);

    __shared__ float sh[8];
    __shared__ float s_rs;
    const int lane = threadIdx.x & 31, wid = threadIdx.x >> 5;
    if (lane == 0) sh[wid] = ss;
    __syncthreads();
    if (threadIdx.x == 0) {
        float tot = 0.f;
        #pragma unroll
        for (int i = 0; i < 8; i++) tot += sh[i];
        s_rs = rsqrtf(tot * (1.0f / D_MODEL) + 1e-6f);
    }
    __syncthreads();
    const float rs = s_rs;
    for (int i = threadIdx.x; i < D_MODEL; i += 256)
        o16[(size_t)t * D_MODEL + i] = __float2half_rn(xr[i] * rs * w[i]);
}

// ---------------------------------------------------------------------------
// fp16 GEMM on mma.sync: C[M,N] = f(A[M,K] @ B[N,K]^T), fp32 accumulate.
//   BM in {128, 64}; BN=128, KC=64, 256 threads, 2-stage cp.async.
//   op: 0 none | 1 bias+softplus | 3 acc+aux | 5 split-K atomicAdd
//   op!=5: gridDim.z==2 batches second (B2, out2) GEMM sharing A.
// ---------------------------------------------------------------------------
template<int BM>
__global__ __launch_bounds__(256) void gemm_h1(
    const __half* __restrict__ Ah,
    const __half* __restrict__ Bh_, const __half* __restrict__ B2h,
    int K, int N,
    float* __restrict__ outF_, float* __restrict__ out2F,
    __half* __restrict__ outH,
    const float* __restrict__ aux, const float* __restrict__ bias, int op)
{
    constexpr int WN  = (BM == 128) ? 2 : 4;
    constexpr int NT  = 128 / WN / 8;            // 8 or 4
    constexpr int ATB = BM * 128;                // BM rows x 64 halves x 2B
    constexpr int BTB = 128 * 128;
    constexpr int STAGE_B = ATB + BTB;

    const bool batched2 = (op != 5) && (blockIdx.z != 0);
    const __half* Bh = batched2 ? B2h : Bh_;
    float* outF = batched2 ? out2F : outF_;

    int k_begin = 0, KL = K;
    if (op == 5) { KL = K / gridDim.z; k_begin = blockIdx.z * KL; }

    extern __shared__ char smem[];
    const uint32_t sb = smem_u32(smem);
    const int tid  = threadIdx.x;
    const int lane = tid & 31;
    const int warp = tid >> 5;
    const int m0 = blockIdx.y * BM;
    const int n0 = blockIdx.x * 128;
    const int wm0 = (warp / WN) * 32;
    const int wn0 = (warp % WN) * (128 / WN);

    const int nch = KL >> 6;

    float acc[2][NT][4];
    #pragma unroll
    for (int mt = 0; mt < 2; mt++)
        #pragma unroll
        for (int nt = 0; nt < NT; nt++)
            #pragma unroll
            for (int r = 0; r < 4; r++) acc[mt][nt][r] = 0.f;

    auto load_stage = [&](int s, int ci) {
        const int k0 = k_begin + (ci << 6);
        const uint32_t sbase = sb + s * STAGE_B;
        #pragma unroll
        for (int arr = 0; arr < 2; arr++) {
            const __half* src = (arr == 0) ? Ah : Bh;
            const int r0 = (arr == 0) ? m0 : n0;
            const int nvec = ((arr == 0) ? BM : 128) * 8;
            const uint32_t abase = sbase + ((arr == 0) ? 0 : ATB);
            #pragma unroll
            for (int jj = 0; jj < nvec / 256; jj++) {
                const int idx = jj * 256 + tid;
                const int row = idx >> 3;
                const int c16 = idx & 7;
                const __half* g = src + (size_t)(r0 + row) * K + k0 + c16 * 8;
                const uint32_t sa = abase + SW128((uint32_t)(row * 128 + c16 * 16));
                CP_ASYNC16(sa, g);
            }
        }
    };

    const int arow = ((lane >> 3) & 1) * 8 + (lane & 7);
    const int akb  = (lane >> 4) * 16;
    const int brow = ((lane >> 4) & 1) * 8 + (lane & 7);
    const int bkb  = ((lane >> 3) & 1) * 16;

    auto compute = [&](int s) {
        const uint32_t sA = sb + s * STAGE_B;
        const uint32_t sB = sA + ATB;
        #pragma unroll
        for (int ks = 0; ks < 4; ks++) {
            uint32_t a_h[2][4], b_h[NT / 2][4];
            #pragma unroll
            for (int mt = 0; mt < 2; mt++) {
                const uint32_t off = SW128(
                    (uint32_t)((wm0 + mt * 16 + arow) * 128 + ks * 32 + akb));
                LDSM4(a_h[mt], sA + off);
            }
            #pragma unroll
            for (int j = 0; j < NT / 2; j++) {
                const uint32_t off = SW128(
                    (uint32_t)((wn0 + j * 16 + brow) * 128 + ks * 32 + bkb));
                LDSM4(b_h[j], sB + off);
            }
            #pragma unroll
            for (int mt = 0; mt < 2; mt++)
                #pragma unroll
                for (int nt = 0; nt < NT; nt++) {
                    const uint32_t bh0 = b_h[nt >> 1][(nt & 1) * 2];
                    const uint32_t bh1 = b_h[nt >> 1][(nt & 1) * 2 + 1];
                    MMA16816(acc[mt][nt], a_h[mt], bh0, bh1);
                }
        }
    };

    load_stage(0, 0); CP_COMMIT();
    load_stage(1, 1); CP_COMMIT();
    for (int i = 0; i < nch; i++) {
        CP_WAIT1();
        __syncthreads();
        compute(i & 1);
        __syncthreads();
        if (i + 2 < nch) load_stage(i & 1, i + 2);
        CP_COMMIT();
    }
    __syncthreads();

    // epilogue via smem for coalesced stores
    float* smC = reinterpret_cast<float*>(smem);   // [BM][132]
    #pragma unroll
    for (int mt = 0; mt < 2; mt++)
        #pragma unroll
        for (int nt = 0; nt < NT; nt++) {
            const int row = wm0 + mt * 16 + (lane >> 2);
            const int col = wn0 + nt * 8 + (lane & 3) * 2;
            *reinterpret_cast<float2*>(&smC[row * 132 + col]) =
                make_float2(acc[mt][nt][0], acc[mt][nt][1]);
            *reinterpret_cast<float2*>(&smC[(row + 8) * 132 + col]) =
                make_float2(acc[mt][nt][2], acc[mt][nt][3]);
        }
    __syncthreads();

    #pragma unroll 4
    for (int e = tid; e < BM * 128; e += 256) {
        const int row = e >> 7, col = e & 127;
        float v = smC[row * 132 + col];
        const size_t ro = (size_t)(m0 + row) * N + (n0 + col);
        if (op == 1) {
            v += bias[n0 + col];
            v = (v > 20.f) ? v : log1pf(__expf(v));
        } else if (op == 3) {
            v += aux[ro];
        } else if (op == 5) {
            atomicAdd(&outF[ro], v);
            continue;
        }
        if (outF) outF[ro] = v;
        if (outH) outH[ro] = __float2half_rn(v);
    }
}

// ---------------------------------------------------------------------------
// Selective scan
// ---------------------------------------------------------------------------
__global__ __launch_bounds__(128) void scan_kernel(
    const float* __restrict__ dt,
    const float* __restrict__ z,
    const float* __restrict__ xdbl,
    const float* __restrict__ A_log,
    const float* __restrict__ D_skip,
    __half* __restrict__ y16)
{
    const int gid = blockIdx.x * blockDim.x + threadIdx.x;
    const int d = gid >> 4;
    const int s = gid & 15;

    const float Aval = -expf(A_log[d * D_STATE + s]);
    const float Dv = D_skip[d];

    const float* Bp = xdbl + DT_RANK + s;
    const float* Cp = xdbl + DT_RANK + D_STATE + s;

    float h = 0.f;
    #pragma unroll 4
    for (int t = 0; t < LSEQ; t++) {
        const float dtv = dt[(size_t)t * D_INNER + d];
        const float zv  = z [(size_t)t * D_INNER + d];
        const float Bv  = Bp[(size_t)t * XPROJ_N];
        const float Cv  = Cp[(size_t)t * XPROJ_N];

        const float abar = __expf(dtv * Aval);
        h = fmaf(abar, h, dtv * zv * Bv);

        float p = h * Cv;
        p += __shfl_xor_sync(0xffffffffu, p, 8);
        p += __shfl_xor_sync(0xffffffffu, p, 4);
        p += __shfl_xor_sync(0xffffffffu, p, 2);
        p += __shfl_xor_sync(0xffffffffu, p, 1);
        if (s == 0)
            y16[(size_t)t * D_INNER + d] = __float2half_rn(p + Dv * zv);
    }
}

// ---------------------------------------------------------------------------
// Launch
// ---------------------------------------------------------------------------
#define SMEM128 (128 * 132 * 4)                       // 67584 (>= 2*32768)
#define SMEM64  (2 * (64 * 128 + 128 * 128))          // 49152 (>= 64*132*4)

extern "C" void kernel_launch(void* const* d_in, const int* in_sizes, int n_in,
                              void* d_out, int out_size)
{
    const float* x        = (const float*)d_in[0];
    const float* w_norm1  = (const float*)d_in[1];
    const float* W_in     = (const float*)d_in[2];
    const float* W_gate   = (const float*)d_in[3];
    const float* W_xproj  = (const float*)d_in[4];
    const float* W_dt     = (const float*)d_in[5];
    const float* b_dt     = (const float*)d_in[6];
    const float* A_log    = (const float*)d_in[7];
    const float* D_skip   = (const float*)d_in[8];
    const float* W_out    = (const float*)d_in[9];
    const float* w_ffn    = (const float*)d_in[10];
    const float* W_up     = (const float*)d_in[11];
    const float* W_gate_f = (const float*)d_in[12];
    const float* W_down   = (const float*)d_in[13];
    float* out = (float*)d_out;

    float *p_lin1, *p_lin2, *p_xdbl, *p_dt, *p_x2, *p_up, *p_gate;
    cudaGetSymbolAddress((void**)&p_lin1, g_lin1);
    cudaGetSymbolAddress((void**)&p_lin2, g_lin2);
    cudaGetSymbolAddress((void**)&p_xdbl, g_xdbl);
    cudaGetSymbolAddress((void**)&p_dt,   g_dt);
    cudaGetSymbolAddress((void**)&p_x2,   g_x2);
    cudaGetSymbolAddress((void**)&p_up,   g_up);
    cudaGetSymbolAddress((void**)&p_gate, g_gate);

    __half *hA,*zA,*xdA,*yA,*hfA,*vA;
    cudaGetSymbolAddress((void**)&hA,  a_h);
    cudaGetSymbolAddress((void**)&zA,  a_z);
    cudaGetSymbolAddress((void**)&xdA, a_xd);
    cudaGetSymbolAddress((void**)&yA,  a_y);
    cudaGetSymbolAddress((void**)&hfA, a_hf);
    cudaGetSymbolAddress((void**)&vA,  a_v);

    __half *winH,*wgtH,*wxH,*wdtH,*woH,*wuH,*wgfH,*wdnH;
    cudaGetSymbolAddress((void**)&winH, w_in_h);
    cudaGetSymbolAddress((void**)&wgtH, w_gt_h);
    cudaGetSymbolAddress((void**)&wxH,  w_x_h);
    cudaGetSymbolAddress((void**)&wdtH, w_dt_h);
    cudaGetSymbolAddress((void**)&woH,  w_out_h);
    cudaGetSymbolAddress((void**)&wuH,  w_up_h);
    cudaGetSymbolAddress((void**)&wgfH, w_gf_h);
    cudaGetSymbolAddress((void**)&wdnH, w_dn_h);

    cudaFuncSetAttribute(gemm_h1<128>, cudaFuncAttributeMaxDynamicSharedMemorySize, SMEM128);
    cudaFuncSetAttribute(gemm_h1<64>,  cudaFuncAttributeMaxDynamicSharedMemorySize, SMEM64);

    const dim3 blk(256);

    // all fp16 weight converts in one launch (+ W_dt pad separately)
    w16_all_kernel<<<(SEG6 + 255) / 256, blk>>>(
        W_in, winH, W_gate, wgtH, W_xproj, wxH, W_out, woH,
        W_up, wuH, W_gate_f, wgfH, W_down, wdnH);
    w16_wdt_kernel<<<(D_INNER * KDT_PAD + 255) / 256, blk>>>(W_dt, wdtH);

    // 1) h = rmsnorm(x)
    rmsnorm_kernel<<<LSEQ, blk>>>(x, w_norm1, hA);

    // 2+3) lin1 = h @ W_in^T ; lin2 = h @ W_gate^T  (batched raw fp32)
    gemm_h1<128><<<dim3(D_INNER / 128, LSEQ / 128, 2), blk, SMEM128>>>(
        hA, winH, wgtH, D_MODEL, D_INNER,
        p_lin1, p_lin2, nullptr, nullptr, nullptr, 0);

    // z = lin1 * sigmoid(lin2)
    gate_kernel<<<(LSEQ * D_INNER / 4 + 255) / 256, blk>>>(
        p_lin1, p_lin2, zA, LSEQ * D_INNER / 4);

    // 4) xdbl = z @ W_xproj^T (split-K = 4, atomic accumulate)
    cudaMemsetAsync(p_xdbl, 0, (size_t)LSEQ * XPROJ_N * sizeof(float));
    gemm_h1<64><<<dim3(XPROJ_N / 128, LSEQ / 64, 4), blk, SMEM64>>>(
        zA, wxH, nullptr, D_INNER, XPROJ_N,
        p_xdbl, nullptr, nullptr, nullptr, nullptr, 5);
    cvt16_kernel<<<(LSEQ * XPROJ_N / 4 + 255) / 256, blk>>>(
        p_xdbl, xdA, LSEQ * XPROJ_N / 4);

    // 5) dt = softplus(xdbl @ W_dt_pad^T + b_dt)
    gemm_h1<128><<<dim3(D_INNER / 128, LSEQ / 128), blk, SMEM128>>>(
        xdA, wdtH, nullptr, KDT_PAD, D_INNER,
        p_dt, nullptr, nullptr, nullptr, b_dt, 1);

    // 6) scan
    scan_kernel<<<(D_INNER * D_STATE) / 128, dim3(128)>>>(
        p_dt, p_lin1, p_xdbl, A_log, D_skip, yA);

    // 7) x2 = x + y @ W_out^T
    gemm_h1<64><<<dim3(D_MODEL / 128, LSEQ / 64), blk, SMEM64>>>(
        yA, woH, nullptr, D_INNER, D_MODEL,
        p_x2, nullptr, nullptr, x, nullptr, 3);

    // 8) hf = rmsnorm(x2)
    rmsnorm_kernel<<<LSEQ, blk>>>(p_x2, w_ffn, hfA);

    // 9+10a) up / gate (batched raw)
    gemm_h1<128><<<dim3(H_FFN / 128, LSEQ / 128, 2), blk, SMEM128>>>(
        hfA, wuH, wgfH, D_MODEL, H_FFN,
        p_up, p_gate, nullptr, nullptr, nullptr, 0);

    // 10b) v = silu(gate) * up
    silu_mul_kernel<<<(LSEQ * H_FFN / 4 + 255) / 256, blk>>>(
        p_up, p_gate, vA, LSEQ * H_FFN / 4);

    // 11) out = x2 + v @ W_down^T
    gemm_h1<64><<<dim3(D_MODEL / 128, LSEQ / 64), blk, SMEM64>>>(
        vA, wdnH, nullptr, H_FFN, D_MODEL,
        out, nullptr, nullptr, p_x2, nullptr, 3);
}